// round 1
// baseline (speedup 1.0000x reference)
#include <cuda_runtime.h>
#include <math.h>

#define HIDDEN 2048
#define NHEADS 16
#define DK 128
#define DR 64
#define DV 128
#define DQK 192
#define B_ 2
#define S_ 2048
#define TOKENS (B_*S_)
#define BH (B_*NHEADS)

// ---------------- scratch (static device memory; allocation-free) ----------------
__device__ float g_c   [TOKENS*512];
__device__ float g_cp  [TOKENS*1536];
__device__ float g_qc  [TOKENS*(NHEADS*DK)];
__device__ float g_qr  [TOKENS*(NHEADS*DR)];
__device__ float g_kc  [TOKENS*(NHEADS*DK)];
__device__ float g_kr  [TOKENS*DR];
__device__ float g_vt  [TOKENS*(NHEADS*DV)];
__device__ float g_Qt  [BH*DQK*S_];      // [bh][d][s]   (transposed for attention)
__device__ float g_Kt  [BH*DQK*S_];      // [bh][d][s]
__device__ float g_V   [BH*S_*DV];       // [bh][s][d]
__device__ float g_attn[TOKENS*(NHEADS*DV)];

// ---------------- generic SGEMM: C[M,N] = A[M,K] @ B[K,N], all row-major -------
// 128x128 block tile, BK=16, 256 threads, 8x8 per-thread microtile.
// Requires M%128==0, N%128==0, K%16==0 (true for every call site).
__global__ void __launch_bounds__(256) sgemm128(const float* __restrict__ A,
        const float* __restrict__ Bm, float* __restrict__ C,
        int M, int N, int K)
{
    __shared__ float As[16][132];   // transposed A tile, padded
    __shared__ float Bs[16][132];
    const int tid = threadIdx.x;
    const int row0 = blockIdx.y * 128, col0 = blockIdx.x * 128;
    const int tx = tid & 15, ty = tid >> 4;
    const int aRow = tid >> 2, aCol = (tid & 3) << 2;
    const int bRow = tid >> 5, bCol = (tid & 31) << 2;
    const float* Ap = A + (size_t)row0 * K;
    const float* Bp = Bm + col0;

    float acc[8][8];
#pragma unroll
    for (int i = 0; i < 8; i++)
#pragma unroll
        for (int j = 0; j < 8; j++) acc[i][j] = 0.f;

    for (int k0 = 0; k0 < K; k0 += 16) {
        float4 a0 = *(const float4*)(Ap + (size_t)aRow * K + k0 + aCol);
        float4 a1 = *(const float4*)(Ap + (size_t)(aRow + 64) * K + k0 + aCol);
        float4 b0 = *(const float4*)(Bp + (size_t)(k0 + bRow) * N + bCol);
        float4 b1 = *(const float4*)(Bp + (size_t)(k0 + bRow + 8) * N + bCol);
        __syncthreads();
        As[aCol + 0][aRow] = a0.x; As[aCol + 1][aRow] = a0.y;
        As[aCol + 2][aRow] = a0.z; As[aCol + 3][aRow] = a0.w;
        As[aCol + 0][aRow + 64] = a1.x; As[aCol + 1][aRow + 64] = a1.y;
        As[aCol + 2][aRow + 64] = a1.z; As[aCol + 3][aRow + 64] = a1.w;
        *(float4*)&Bs[bRow][bCol]     = b0;
        *(float4*)&Bs[bRow + 8][bCol] = b1;
        __syncthreads();
#pragma unroll
        for (int k = 0; k < 16; k++) {
            float4 ra0 = *(const float4*)&As[k][ty * 8];
            float4 ra1 = *(const float4*)&As[k][ty * 8 + 4];
            float4 rb0 = *(const float4*)&Bs[k][tx * 8];
            float4 rb1 = *(const float4*)&Bs[k][tx * 8 + 4];
            float ra[8] = {ra0.x, ra0.y, ra0.z, ra0.w, ra1.x, ra1.y, ra1.z, ra1.w};
            float rb[8] = {rb0.x, rb0.y, rb0.z, rb0.w, rb1.x, rb1.y, rb1.z, rb1.w};
#pragma unroll
            for (int i = 0; i < 8; i++)
#pragma unroll
                for (int j = 0; j < 8; j++) acc[i][j] += ra[i] * rb[j];
        }
    }
#pragma unroll
    for (int i = 0; i < 8; i++) {
        float* cp = C + (size_t)(row0 + ty * 8 + i) * N + col0 + tx * 8;
        *(float4*)cp       = make_float4(acc[i][0], acc[i][1], acc[i][2], acc[i][3]);
        *(float4*)(cp + 4) = make_float4(acc[i][4], acc[i][5], acc[i][6], acc[i][7]);
    }
}

// ---------------- skinny projection: out[tok,64] = x[tok,2048] @ Wkr[2048,64] ----
__global__ void __launch_bounds__(256) kr_proj(const float* __restrict__ x,
        const float* __restrict__ Wkr, float* __restrict__ out)
{
    __shared__ float sx[4][HIDDEN];
    const int t0 = blockIdx.x * 4;
    for (int f = threadIdx.x; f < 4 * HIDDEN / 4; f += 256) {
        int row = f >> 9, c4 = f & 511;
        ((float4*)sx[row])[c4] = ((const float4*)(x + (size_t)(t0 + row) * HIDDEN))[c4];
    }
    __syncthreads();
    const int n = threadIdx.x & 63, tl = threadIdx.x >> 6;
    float s = 0.f;
#pragma unroll 8
    for (int k = 0; k < HIDDEN; k++) s += sx[tl][k] * Wkr[k * 64 + n];
    out[(size_t)(t0 + tl) * 64 + n] = s;
}

// ---------------- pack q/k: concat [c_part(128) | rope(r_part)(64)], emit transposed
// Out[bh][d][s].  For q: rRowStride=H*64, rHeadStride=64.  For k: 64, 0.
__global__ void __launch_bounds__(256) pack_qk(const float* __restrict__ cbuf,
        const float* __restrict__ rbuf, int rRowStride, int rHeadStride,
        float* __restrict__ Out)
{
    __shared__ float tile[32][193];
    __shared__ float sinv[32];
    const int bh = blockIdx.y, b = bh >> 4, h = bh & 15;
    const int s0 = blockIdx.x * 32;
    if (threadIdx.x < 32)
        sinv[threadIdx.x] = (float)pow(10000.0, -(double)threadIdx.x / 32.0);
    __syncthreads();
    for (int f = threadIdx.x; f < 32 * DQK; f += 256) {
        int row = f / DQK, d = f % DQK;
        size_t tok = (size_t)b * S_ + s0 + row;
        float val;
        if (d < 128) {
            val = cbuf[tok * (NHEADS * 128) + h * 128 + d];
        } else {
            int dd = d - 128, i = dd >> 1;
            const float* rp = rbuf + tok * rRowStride + h * rHeadStride;
            float re = rp[2 * i], im = rp[2 * i + 1];
            float ang = (float)(s0 + row) * sinv[i];
            float cs = cosf(ang), sn = sinf(ang);
            val = (dd & 1) ? (re * sn + im * cs) : (re * cs - im * sn);
        }
        tile[row][d] = val;
    }
    __syncthreads();
    for (int f = threadIdx.x; f < DQK * 32; f += 256) {
        int d = f >> 5, c = f & 31;
        Out[((size_t)bh * DQK + d) * S_ + s0 + c] = tile[c][d];
    }
}

// ---------------- pack v: [tok][h*128+d] -> [bh][s][d] -------------------------
__global__ void __launch_bounds__(256) pack_v(const float* __restrict__ vt,
        float* __restrict__ Vo)
{
    const int bh = blockIdx.y, b = bh >> 4, h = bh & 15;
    const int s0 = blockIdx.x * 64;
    for (int f = threadIdx.x; f < 64 * 128; f += 256) {
        int r = f >> 7, d = f & 127;
        Vo[((size_t)bh * S_ + s0 + r) * 128 + d] =
            vt[((size_t)(b * S_ + s0 + r)) * (NHEADS * 128) + h * 128 + d];
    }
}

// ---------------- causal flash attention, fp32, 64x64 tiles --------------------
// Qt,Kt: [bh][192][S]; V: [bh][S][128]; O: [tok][H*128]
__global__ void __launch_bounds__(256) attn_kernel(const float* __restrict__ Qt,
        const float* __restrict__ Kt, const float* __restrict__ V,
        float* __restrict__ O)
{
    extern __shared__ float smem[];
    float* sQ = smem;              // [192][64]
    float* sK = sQ + DQK * 64;     // [192][64]
    float* sV = sK + DQK * 64;     // [64][128]
    float* sP = sV + 64 * DV;      // [64][64]

    const int tid = threadIdx.x, lane = tid & 31, warp = tid >> 5;
    const int bh = blockIdx.y;
    const int qt = gridDim.x - 1 - blockIdx.x;   // big tiles first (load balance)
    const int q0 = qt * 64;
    const float scale = 1.0f / sqrtf((float)DQK);
    const float NEG_INF = -__int_as_float(0x7f800000);

    const float* qg = Qt + (size_t)bh * DQK * S_ + q0;
    for (int f = tid; f < DQK * 64; f += 256)
        sQ[f] = qg[(size_t)(f >> 6) * S_ + (f & 63)];

    float acc[8][4], m[8], l[8];
#pragma unroll
    for (int r = 0; r < 8; r++) {
        m[r] = NEG_INF; l[r] = 0.f;
        acc[r][0] = acc[r][1] = acc[r][2] = acc[r][3] = 0.f;
    }

    for (int kt = 0; kt <= qt; kt++) {
        __syncthreads();
        const float* kg = Kt + (size_t)bh * DQK * S_ + kt * 64;
        for (int f = tid; f < DQK * 64; f += 256)
            sK[f] = kg[(size_t)(f >> 6) * S_ + (f & 63)];
        const float* vg = V + ((size_t)bh * S_ + kt * 64) * DV;
        for (int f = tid; f < 64 * DV; f += 256) sV[f] = vg[f];
        __syncthreads();

        // S = Q @ K^T : each thread computes 8 rows x 2 cols
        float sv0[8], sv1[8];
#pragma unroll
        for (int r = 0; r < 8; r++) { sv0[r] = 0.f; sv1[r] = 0.f; }
#pragma unroll 8
        for (int k = 0; k < DQK; k++) {
            float2 kk = *(const float2*)&sK[k * 64 + lane * 2];
            float4 qa = *(const float4*)&sQ[k * 64 + warp * 8];
            float4 qb = *(const float4*)&sQ[k * 64 + warp * 8 + 4];
            sv0[0] += qa.x * kk.x; sv1[0] += qa.x * kk.y;
            sv0[1] += qa.y * kk.x; sv1[1] += qa.y * kk.y;
            sv0[2] += qa.z * kk.x; sv1[2] += qa.z * kk.y;
            sv0[3] += qa.w * kk.x; sv1[3] += qa.w * kk.y;
            sv0[4] += qb.x * kk.x; sv1[4] += qb.x * kk.y;
            sv0[5] += qb.y * kk.x; sv1[5] += qb.y * kk.y;
            sv0[6] += qb.z * kk.x; sv1[6] += qb.z * kk.y;
            sv0[7] += qb.w * kk.x; sv1[7] += qb.w * kk.y;
        }

        const bool diag = (kt == qt);
#pragma unroll
        for (int r = 0; r < 8; r++) {
            float s0 = sv0[r] * scale, s1 = sv1[r] * scale;
            int row = warp * 8 + r;
            if (diag) {
                if (lane * 2     > row) s0 = NEG_INF;
                if (lane * 2 + 1 > row) s1 = NEG_INF;
            }
            float mr = fmaxf(s0, s1);
#pragma unroll
            for (int o = 16; o > 0; o >>= 1)
                mr = fmaxf(mr, __shfl_xor_sync(0xffffffffu, mr, o));
            float nm = fmaxf(m[r], mr);
            float corr = __expf(m[r] - nm);
            float p0 = __expf(s0 - nm), p1 = __expf(s1 - nm);
            float rs = p0 + p1;
#pragma unroll
            for (int o = 16; o > 0; o >>= 1)
                rs += __shfl_xor_sync(0xffffffffu, rs, o);
            l[r] = l[r] * corr + rs;
            m[r] = nm;
            acc[r][0] *= corr; acc[r][1] *= corr;
            acc[r][2] *= corr; acc[r][3] *= corr;
            *(float2*)&sP[row * 64 + lane * 2] = make_float2(p0, p1);
        }
        __syncwarp();

        // O += P @ V : each thread owns 8 rows x 4 cols
#pragma unroll 4
        for (int j = 0; j < 64; j++) {
            float4 v4 = *(const float4*)&sV[j * DV + lane * 4];
#pragma unroll
            for (int r = 0; r < 8; r++) {
                float p = sP[(warp * 8 + r) * 64 + j];
                acc[r][0] += p * v4.x; acc[r][1] += p * v4.y;
                acc[r][2] += p * v4.z; acc[r][3] += p * v4.w;
            }
        }
    }

    const int b = bh >> 4, h = bh & 15;
#pragma unroll
    for (int r = 0; r < 8; r++) {
        float inv = 1.f / l[r];
        int row = q0 + warp * 8 + r;
        float4 o4 = make_float4(acc[r][0] * inv, acc[r][1] * inv,
                                acc[r][2] * inv, acc[r][3] * inv);
        *(float4*)&O[((size_t)(b * S_) + row) * (size_t)(NHEADS * DV) + h * DV + lane * 4] = o4;
    }
}

// ---------------- orchestration -------------------------------------------------
extern "C" void kernel_launch(void* const* d_in, const int* in_sizes, int n_in,
                              void* d_out, int out_size)
{
    const float* x    = (const float*)d_in[0];
    const float* W_c  = (const float*)d_in[1];
    const float* W_cp = (const float*)d_in[2];
    const float* W_qc = (const float*)d_in[3];
    const float* W_qr = (const float*)d_in[4];
    const float* W_kc = (const float*)d_in[5];
    const float* W_kr = (const float*)d_in[6];
    const float* W_v  = (const float*)d_in[7];
    const float* W_o  = (const float*)d_in[8];
    float* out = (float*)d_out;

    float *c, *cp, *qc, *qr, *kc, *kr, *vt, *Qt, *Kt, *V, *attn;
    cudaGetSymbolAddress((void**)&c,    g_c);
    cudaGetSymbolAddress((void**)&cp,   g_cp);
    cudaGetSymbolAddress((void**)&qc,   g_qc);
    cudaGetSymbolAddress((void**)&qr,   g_qr);
    cudaGetSymbolAddress((void**)&kc,   g_kc);
    cudaGetSymbolAddress((void**)&kr,   g_kr);
    cudaGetSymbolAddress((void**)&vt,   g_vt);
    cudaGetSymbolAddress((void**)&Qt,   g_Qt);
    cudaGetSymbolAddress((void**)&Kt,   g_Kt);
    cudaGetSymbolAddress((void**)&V,    g_V);
    cudaGetSymbolAddress((void**)&attn, g_attn);

    const int attn_smem = (DQK * 64 * 2 + 64 * DV + 64 * 64) * 4;   // 147456 B
    cudaFuncSetAttribute(attn_kernel,
                         cudaFuncAttributeMaxDynamicSharedMemorySize, attn_smem);

    dim3 blk(256);
    // latent projections
    sgemm128<<<dim3(1536 / 128, TOKENS / 128), blk>>>(x, W_cp, cp, TOKENS, 1536, HIDDEN);
    sgemm128<<<dim3(512  / 128, TOKENS / 128), blk>>>(x, W_c,  c,  TOKENS, 512,  HIDDEN);
    kr_proj<<<TOKENS / 4, blk>>>(x, W_kr, kr);
    // q/k/v heads
    sgemm128<<<dim3(2048 / 128, TOKENS / 128), blk>>>(cp, W_qc, qc, TOKENS, 2048, 1536);
    sgemm128<<<dim3(1024 / 128, TOKENS / 128), blk>>>(cp, W_qr, qr, TOKENS, 1024, 1536);
    sgemm128<<<dim3(2048 / 128, TOKENS / 128), blk>>>(c,  W_kc, kc, TOKENS, 2048, 512);
    sgemm128<<<dim3(2048 / 128, TOKENS / 128), blk>>>(c,  W_v,  vt, TOKENS, 2048, 512);
    // pack + rope (q/k transposed for the attention kernel)
    pack_qk<<<dim3(S_ / 32, BH), blk>>>(qc, qr, NHEADS * DR, DR, Qt);
    pack_qk<<<dim3(S_ / 32, BH), blk>>>(kc, kr, DR, 0, Kt);
    pack_v <<<dim3(S_ / 64, BH), blk>>>(vt, V);
    // causal attention
    attn_kernel<<<dim3(S_ / 64, BH), blk, attn_smem>>>(Qt, Kt, V, attn);
    // output projection
    sgemm128<<<dim3(2048 / 128, TOKENS / 128), blk>>>(attn, W_o, out, TOKENS, 2048, 2048);
}

// round 7
// speedup vs baseline: 1.5157x; 1.5157x over previous
#include <cuda_runtime.h>
#include <cuda_bf16.h>
#include <math.h>
#include <stdint.h>

#define HIDDEN 2048
#define NHEADS 16
#define DK 128
#define DR 64
#define DV 128
#define DQK 192
#define B_ 2
#define S_ 2048
#define TOKENS (B_*S_)
#define BH (B_*NHEADS)

// ---------------- scratch (static device memory; allocation-free) ----------------
__device__ float g_c   [TOKENS*512];
__device__ float g_cp  [TOKENS*1536];
__device__ float g_qc  [TOKENS*(NHEADS*DK)];
__device__ float g_qr  [TOKENS*(NHEADS*DR)];
__device__ float g_kc  [TOKENS*(NHEADS*DK)];
__device__ float g_kr  [TOKENS*DR];
__device__ float g_vt  [TOKENS*(NHEADS*DV)];
__device__ float g_Qt  [BH*DQK*S_];
__device__ float g_Kt  [BH*DQK*S_];
__device__ float g_V   [BH*S_*DV];
__device__ float g_attn[TOKENS*(NHEADS*DV)];

// bf16 hi/lo split activations
__device__ __align__(16) __nv_bfloat16 g_xh [TOKENS*HIDDEN];
__device__ __align__(16) __nv_bfloat16 g_xl [TOKENS*HIDDEN];
__device__ __align__(16) __nv_bfloat16 g_cph[TOKENS*1536];
__device__ __align__(16) __nv_bfloat16 g_cpl[TOKENS*1536];
__device__ __align__(16) __nv_bfloat16 g_ch [TOKENS*512];
__device__ __align__(16) __nv_bfloat16 g_cl [TOKENS*512];
__device__ __align__(16) __nv_bfloat16 g_ah [TOKENS*2048];
__device__ __align__(16) __nv_bfloat16 g_al [TOKENS*2048];
// bf16 hi/lo transposed weights: Wt[N][K] = W[K][N]
__device__ __align__(16) __nv_bfloat16 g_wcp_h[1536*2048], g_wcp_l[1536*2048];
__device__ __align__(16) __nv_bfloat16 g_wc_h [512*2048],  g_wc_l [512*2048];
__device__ __align__(16) __nv_bfloat16 g_wqc_h[2048*1536], g_wqc_l[2048*1536];
__device__ __align__(16) __nv_bfloat16 g_wqr_h[1024*1536], g_wqr_l[1024*1536];
__device__ __align__(16) __nv_bfloat16 g_wkc_h[2048*512],  g_wkc_l[2048*512];
__device__ __align__(16) __nv_bfloat16 g_wv_h [2048*512],  g_wv_l [2048*512];
__device__ __align__(16) __nv_bfloat16 g_wo_h [2048*2048], g_wo_l [2048*2048];

// ======================= mma.sync helpers (base sm_103, no 'a' features) ========
__device__ __forceinline__ uint32_t smem_u32(const void* p) {
    return (uint32_t)__cvta_generic_to_shared(p);
}
__device__ __forceinline__ void ldsm4(uint32_t* r, uint32_t addr) {
    asm volatile("ldmatrix.sync.aligned.m8n8.x4.shared.b16 {%0,%1,%2,%3}, [%4];"
        : "=r"(r[0]), "=r"(r[1]), "=r"(r[2]), "=r"(r[3]) : "r"(addr));
}
__device__ __forceinline__ void mma16816(float* d, const uint32_t* a,
                                         uint32_t b0, uint32_t b1) {
    asm volatile("mma.sync.aligned.m16n8k16.row.col.f32.bf16.bf16.f32 "
        "{%0,%1,%2,%3}, {%4,%5,%6,%7}, {%8,%9}, {%0,%1,%2,%3};"
        : "+f"(d[0]), "+f"(d[1]), "+f"(d[2]), "+f"(d[3])
        : "r"(a[0]), "r"(a[1]), "r"(a[2]), "r"(a[3]), "r"(b0), "r"(b1));
}

// ======================= tensor-core GEMM: C[M,N] = A[M,K] @ Bt[N,K]^T ==========
// A (hi/lo) [M,K] bf16 K-major, Bt (hi/lo) [N,K] bf16 K-major, C fp32 row-major.
// CTA tile 128x128, K-chunk 64, single-buffered SMEM (64KB), 2 CTAs/SM.
// bf16x3: C += Ah*Bh + Ah*Bl + Al*Bh.
#define MG_SMEM 65536

__global__ void __launch_bounds__(256, 2) mma_gemm(
        const __nv_bfloat16* __restrict__ Ahg, const __nv_bfloat16* __restrict__ Alg,
        const __nv_bfloat16* __restrict__ Bhg, const __nv_bfloat16* __restrict__ Blg,
        float* __restrict__ C, int M, int N, int K)
{
    extern __shared__ char smem[];   // [Ah | Al | Bh | Bl], each 128 rows x 128B, SW128
    const uint32_t sb = smem_u32(smem);
    const int tid = threadIdx.x, wid = tid >> 5, lane = tid & 31;
    const int m0 = blockIdx.y * 128, n0 = blockIdx.x * 128;
    const int wm = (wid & 1) * 64;      // warp tile 64x32
    const int wn = (wid >> 1) * 32;

    float acc[16][4];
#pragma unroll
    for (int i = 0; i < 16; i++)
#pragma unroll
        for (int j = 0; j < 4; j++) acc[i][j] = 0.f;

    // ldmatrix per-thread geometry
    const int aRow  = lane & 15;              // + mt*16 + wm
    const int aCsel = (lane >> 4) * 16;       // byte offset within 32B k-step pair
    const int bRow  = (lane & 7) + ((lane >> 4) << 3);   // n within 16
    const int bCsel = ((lane >> 3) & 1) * 16;

    for (int k0 = 0; k0 < K; k0 += 64) {
        __syncthreads();
        // ---- stage 4 tiles: 16 x uint4 per thread ----
#pragma unroll
        for (int j = 0; j < 16; j++) {
            const int t = j >> 2;
            const int idx = (j & 3) * 256 + tid;      // 0..1023
            const int r = idx >> 3, jc = idx & 7;
            const __nv_bfloat16* g = (t == 0) ? Ahg : (t == 1) ? Alg
                                   : (t == 2) ? Bhg : Blg;
            const int row = ((t < 2) ? m0 : n0) + r;
            const uint4 v = *(const uint4*)(g + (size_t)row * K + k0 + jc * 8);
            const uint32_t off = (uint32_t)(r * 128 + ((jc * 16) ^ ((r & 7) << 4)));
            *(uint4*)(smem + t * 16384 + off) = v;
        }
        __syncthreads();

        const uint32_t bAh = sb, bAl = sb + 16384, bBh = sb + 32768, bBl = sb + 49152;
#pragma unroll
        for (int ks = 0; ks < 4; ks++) {
            uint32_t ah[4][4], bh[2][4];
            // Ah fragments: 4 m-tiles
#pragma unroll
            for (int mt = 0; mt < 4; mt++) {
                const int r = wm + mt * 16 + aRow;
                const uint32_t off = r * 128 + ((ks * 32 + aCsel) ^ ((r & 7) << 4));
                ldsm4(ah[mt], bAh + off);
            }
            // Bh fragments: 2 n-pairs (each covers two n8 tiles)
#pragma unroll
            for (int np = 0; np < 2; np++) {
                const int r = wn + np * 16 + bRow;
                const uint32_t off = r * 128 + ((ks * 32 + bCsel) ^ ((r & 7) << 4));
                ldsm4(bh[np], bBh + off);
            }
            // Ah * Bh
#pragma unroll
            for (int mt = 0; mt < 4; mt++)
#pragma unroll
                for (int nt = 0; nt < 4; nt++)
                    mma16816(acc[mt * 4 + nt], ah[mt],
                             bh[nt >> 1][(nt & 1) * 2], bh[nt >> 1][(nt & 1) * 2 + 1]);
            // Ah * Bl
            {
                uint32_t bl[2][4];
#pragma unroll
                for (int np = 0; np < 2; np++) {
                    const int r = wn + np * 16 + bRow;
                    const uint32_t off = r * 128 + ((ks * 32 + bCsel) ^ ((r & 7) << 4));
                    ldsm4(bl[np], bBl + off);
                }
#pragma unroll
                for (int mt = 0; mt < 4; mt++)
#pragma unroll
                    for (int nt = 0; nt < 4; nt++)
                        mma16816(acc[mt * 4 + nt], ah[mt],
                                 bl[nt >> 1][(nt & 1) * 2], bl[nt >> 1][(nt & 1) * 2 + 1]);
            }
            // Al * Bh
            {
                uint32_t al[4][4];
#pragma unroll
                for (int mt = 0; mt < 4; mt++) {
                    const int r = wm + mt * 16 + aRow;
                    const uint32_t off = r * 128 + ((ks * 32 + aCsel) ^ ((r & 7) << 4));
                    ldsm4(al[mt], bAl + off);
                }
#pragma unroll
                for (int mt = 0; mt < 4; mt++)
#pragma unroll
                    for (int nt = 0; nt < 4; nt++)
                        mma16816(acc[mt * 4 + nt], al[mt],
                                 bh[nt >> 1][(nt & 1) * 2], bh[nt >> 1][(nt & 1) * 2 + 1]);
            }
        }
    }

    // ---- epilogue: fragment layout d0,d1 = (row, col..col+1), d2,d3 = row+8 ----
    const int er = lane >> 2, ec = (lane & 3) * 2;
#pragma unroll
    for (int mt = 0; mt < 4; mt++)
#pragma unroll
        for (int nt = 0; nt < 4; nt++) {
            const int row = m0 + wm + mt * 16 + er;
            const int col = n0 + wn + nt * 8 + ec;
            float* cp = C + (size_t)row * N + col;
            *(float2*)cp = make_float2(acc[mt * 4 + nt][0], acc[mt * 4 + nt][1]);
            *(float2*)(cp + (size_t)8 * N) = make_float2(acc[mt * 4 + nt][2], acc[mt * 4 + nt][3]);
        }
}

// ---------------- fp32 -> bf16 hi/lo split (elementwise) -----------------------
__global__ void __launch_bounds__(256) split_f32(const float* __restrict__ in,
        __nv_bfloat16* __restrict__ hi, __nv_bfloat16* __restrict__ lo, int n4)
{
    const int i = blockIdx.x * 256 + threadIdx.x;
    if (i >= n4) return;
    const float4 v = ((const float4*)in)[i];
    float xs[4] = {v.x, v.y, v.z, v.w};
    union { __nv_bfloat16 b[4]; uint2 u; } H, L;
#pragma unroll
    for (int j = 0; j < 4; j++) {
        __nv_bfloat16 h = __float2bfloat16(xs[j]);
        H.b[j] = h;
        L.b[j] = __float2bfloat16(xs[j] - __bfloat162float(h));
    }
    ((uint2*)hi)[i] = H.u;
    ((uint2*)lo)[i] = L.u;
}

// ---------------- fp32 W[K,N] -> bf16 hi/lo Wt[N,K] (transpose split) ----------
__global__ void __launch_bounds__(256) split_tr(const float* __restrict__ W,
        __nv_bfloat16* __restrict__ hi, __nv_bfloat16* __restrict__ lo, int K, int N)
{
    __shared__ float t[32][33];
    const int n0 = blockIdx.x * 32, k0 = blockIdx.y * 32;
    const int tx = threadIdx.x & 31, ty = threadIdx.x >> 5;
#pragma unroll
    for (int rr = 0; rr < 32; rr += 8)
        t[ty + rr][tx] = W[(size_t)(k0 + ty + rr) * N + n0 + tx];
    __syncthreads();
#pragma unroll
    for (int rr = 0; rr < 32; rr += 8) {
        const float x = t[tx][ty + rr];
        const __nv_bfloat16 h = __float2bfloat16(x);
        const size_t o = (size_t)(n0 + ty + rr) * K + k0 + tx;
        hi[o] = h;
        lo[o] = __float2bfloat16(x - __bfloat162float(h));
    }
}

// ---------------- skinny projection: out[tok,64] = x[tok,2048] @ Wkr[2048,64] ----
__global__ void __launch_bounds__(256) kr_proj(const float* __restrict__ x,
        const float* __restrict__ Wkr, float* __restrict__ out)
{
    __shared__ float sx[4][HIDDEN];
    const int t0 = blockIdx.x * 4;
    for (int f = threadIdx.x; f < 4 * HIDDEN / 4; f += 256) {
        int row = f >> 9, c4 = f & 511;
        ((float4*)sx[row])[c4] = ((const float4*)(x + (size_t)(t0 + row) * HIDDEN))[c4];
    }
    __syncthreads();
    const int n = threadIdx.x & 63, tl = threadIdx.x >> 6;
    float s = 0.f;
#pragma unroll 8
    for (int k = 0; k < HIDDEN; k++) s += sx[tl][k] * Wkr[k * 64 + n];
    out[(size_t)(t0 + tl) * 64 + n] = s;
}

// ---------------- pack q/k: concat [c_part(128) | rope(r_part)(64)], transposed --
__global__ void __launch_bounds__(256) pack_qk(const float* __restrict__ cbuf,
        const float* __restrict__ rbuf, int rRowStride, int rHeadStride,
        float* __restrict__ Out)
{
    __shared__ float tile[32][193];
    __shared__ float sinv[32];
    const int bh = blockIdx.y, b = bh >> 4, h = bh & 15;
    const int s0 = blockIdx.x * 32;
    if (threadIdx.x < 32)
        sinv[threadIdx.x] = (float)pow(10000.0, -(double)threadIdx.x / 32.0);
    __syncthreads();
    for (int f = threadIdx.x; f < 32 * DQK; f += 256) {
        int row = f / DQK, d = f % DQK;
        size_t tok = (size_t)b * S_ + s0 + row;
        float val;
        if (d < 128) {
            val = cbuf[tok * (NHEADS * 128) + h * 128 + d];
        } else {
            int dd = d - 128, i = dd >> 1;
            const float* rp = rbuf + tok * rRowStride + h * rHeadStride;
            float re = rp[2 * i], im = rp[2 * i + 1];
            float ang = (float)(s0 + row) * sinv[i];
            float cs = cosf(ang), sn = sinf(ang);
            val = (dd & 1) ? (re * sn + im * cs) : (re * cs - im * sn);
        }
        tile[row][d] = val;
    }
    __syncthreads();
    for (int f = threadIdx.x; f < DQK * 32; f += 256) {
        int d = f >> 5, c = f & 31;
        Out[((size_t)bh * DQK + d) * S_ + s0 + c] = tile[c][d];
    }
}

// ---------------- pack v: [tok][h*128+d] -> [bh][s][d] -------------------------
__global__ void __launch_bounds__(256) pack_v(const float* __restrict__ vt,
        float* __restrict__ Vo)
{
    const int bh = blockIdx.y, b = bh >> 4, h = bh & 15;
    const int s0 = blockIdx.x * 64;
    for (int f = threadIdx.x; f < 64 * 128; f += 256) {
        int r = f >> 7, d = f & 127;
        Vo[((size_t)bh * S_ + s0 + r) * 128 + d] =
            vt[((size_t)(b * S_ + s0 + r)) * (NHEADS * 128) + h * 128 + d];
    }
}

// ---------------- causal flash attention, fp32, 64x64 tiles --------------------
__global__ void __launch_bounds__(256) attn_kernel(const float* __restrict__ Qt,
        const float* __restrict__ Kt, const float* __restrict__ V,
        float* __restrict__ O)
{
    extern __shared__ float fsm[];
    float* sQ = fsm;
    float* sK = sQ + DQK * 64;
    float* sV = sK + DQK * 64;
    float* sP = sV + 64 * DV;

    const int tid = threadIdx.x, lane = tid & 31, warp = tid >> 5;
    const int bh = blockIdx.y;
    const int qt = gridDim.x - 1 - blockIdx.x;
    const int q0 = qt * 64;
    const float scale = 1.0f / sqrtf((float)DQK);
    const float NEG_INF = -__int_as_float(0x7f800000);

    const float* qg = Qt + (size_t)bh * DQK * S_ + q0;
    for (int f = tid; f < DQK * 64; f += 256)
        sQ[f] = qg[(size_t)(f >> 6) * S_ + (f & 63)];

    float acc[8][4], m[8], l[8];
#pragma unroll
    for (int r = 0; r < 8; r++) {
        m[r] = NEG_INF; l[r] = 0.f;
        acc[r][0] = acc[r][1] = acc[r][2] = acc[r][3] = 0.f;
    }

    for (int kt = 0; kt <= qt; kt++) {
        __syncthreads();
        const float* kg = Kt + (size_t)bh * DQK * S_ + kt * 64;
        for (int f = tid; f < DQK * 64; f += 256)
            sK[f] = kg[(size_t)(f >> 6) * S_ + (f & 63)];
        const float* vg = V + ((size_t)bh * S_ + kt * 64) * DV;
        for (int f = tid; f < 64 * DV; f += 256) sV[f] = vg[f];
        __syncthreads();

        float sv0[8], sv1[8];
#pragma unroll
        for (int r = 0; r < 8; r++) { sv0[r] = 0.f; sv1[r] = 0.f; }
#pragma unroll 8
        for (int k = 0; k < DQK; k++) {
            float2 kk = *(const float2*)&sK[k * 64 + lane * 2];
            float4 qa = *(const float4*)&sQ[k * 64 + warp * 8];
            float4 qb = *(const float4*)&sQ[k * 64 + warp * 8 + 4];
            sv0[0] += qa.x * kk.x; sv1[0] += qa.x * kk.y;
            sv0[1] += qa.y * kk.x; sv1[1] += qa.y * kk.y;
            sv0[2] += qa.z * kk.x; sv1[2] += qa.z * kk.y;
            sv0[3] += qa.w * kk.x; sv1[3] += qa.w * kk.y;
            sv0[4] += qb.x * kk.x; sv1[4] += qb.x * kk.y;
            sv0[5] += qb.y * kk.x; sv1[5] += qb.y * kk.y;
            sv0[6] += qb.z * kk.x; sv1[6] += qb.z * kk.y;
            sv0[7] += qb.w * kk.x; sv1[7] += qb.w * kk.y;
        }

        const bool diag = (kt == qt);
#pragma unroll
        for (int r = 0; r < 8; r++) {
            float s0 = sv0[r] * scale, s1 = sv1[r] * scale;
            int row = warp * 8 + r;
            if (diag) {
                if (lane * 2     > row) s0 = NEG_INF;
                if (lane * 2 + 1 > row) s1 = NEG_INF;
            }
            float mr = fmaxf(s0, s1);
#pragma unroll
            for (int o = 16; o > 0; o >>= 1)
                mr = fmaxf(mr, __shfl_xor_sync(0xffffffffu, mr, o));
            float nm = fmaxf(m[r], mr);
            float corr = __expf(m[r] - nm);
            float p0 = __expf(s0 - nm), p1 = __expf(s1 - nm);
            float rs = p0 + p1;
#pragma unroll
            for (int o = 16; o > 0; o >>= 1)
                rs += __shfl_xor_sync(0xffffffffu, rs, o);
            l[r] = l[r] * corr + rs;
            m[r] = nm;
            acc[r][0] *= corr; acc[r][1] *= corr;
            acc[r][2] *= corr; acc[r][3] *= corr;
            *(float2*)&sP[row * 64 + lane * 2] = make_float2(p0, p1);
        }
        __syncwarp();

#pragma unroll 4
        for (int j = 0; j < 64; j++) {
            float4 v4 = *(const float4*)&sV[j * DV + lane * 4];
#pragma unroll
            for (int r = 0; r < 8; r++) {
                float p = sP[(warp * 8 + r) * 64 + j];
                acc[r][0] += p * v4.x; acc[r][1] += p * v4.y;
                acc[r][2] += p * v4.z; acc[r][3] += p * v4.w;
            }
        }
    }

    const int b = bh >> 4, h = bh & 15;
#pragma unroll
    for (int r = 0; r < 8; r++) {
        float inv = 1.f / l[r];
        int row = q0 + warp * 8 + r;
        float4 o4 = make_float4(acc[r][0] * inv, acc[r][1] * inv,
                                acc[r][2] * inv, acc[r][3] * inv);
        *(float4*)&O[((size_t)(b * S_) + row) * (size_t)(NHEADS * DV) + h * DV + lane * 4] = o4;
    }
}

// ---------------- orchestration -------------------------------------------------
extern "C" void kernel_launch(void* const* d_in, const int* in_sizes, int n_in,
                              void* d_out, int out_size)
{
    const float* x    = (const float*)d_in[0];
    const float* W_c  = (const float*)d_in[1];
    const float* W_cp = (const float*)d_in[2];
    const float* W_qc = (const float*)d_in[3];
    const float* W_qr = (const float*)d_in[4];
    const float* W_kc = (const float*)d_in[5];
    const float* W_kr = (const float*)d_in[6];
    const float* W_v  = (const float*)d_in[7];
    const float* W_o  = (const float*)d_in[8];
    float* out = (float*)d_out;

    float *c, *cp, *qc, *qr, *kc, *kr, *vt, *Qt, *Kt, *V, *attn;
    cudaGetSymbolAddress((void**)&c,    g_c);
    cudaGetSymbolAddress((void**)&cp,   g_cp);
    cudaGetSymbolAddress((void**)&qc,   g_qc);
    cudaGetSymbolAddress((void**)&qr,   g_qr);
    cudaGetSymbolAddress((void**)&kc,   g_kc);
    cudaGetSymbolAddress((void**)&kr,   g_kr);
    cudaGetSymbolAddress((void**)&vt,   g_vt);
    cudaGetSymbolAddress((void**)&Qt,   g_Qt);
    cudaGetSymbolAddress((void**)&Kt,   g_Kt);
    cudaGetSymbolAddress((void**)&V,    g_V);
    cudaGetSymbolAddress((void**)&attn, g_attn);

    __nv_bfloat16 *xh,*xl,*cph,*cpl,*ch,*cl,*ah,*al;
    __nv_bfloat16 *wcph,*wcpl,*wch,*wcl,*wqch,*wqcl,*wqrh,*wqrl,*wkch,*wkcl,*wvh,*wvl,*woh,*wol;
    cudaGetSymbolAddress((void**)&xh,  g_xh);   cudaGetSymbolAddress((void**)&xl,  g_xl);
    cudaGetSymbolAddress((void**)&cph, g_cph);  cudaGetSymbolAddress((void**)&cpl, g_cpl);
    cudaGetSymbolAddress((void**)&ch,  g_ch);   cudaGetSymbolAddress((void**)&cl,  g_cl);
    cudaGetSymbolAddress((void**)&ah,  g_ah);   cudaGetSymbolAddress((void**)&al,  g_al);
    cudaGetSymbolAddress((void**)&wcph,g_wcp_h);cudaGetSymbolAddress((void**)&wcpl,g_wcp_l);
    cudaGetSymbolAddress((void**)&wch, g_wc_h); cudaGetSymbolAddress((void**)&wcl, g_wc_l);
    cudaGetSymbolAddress((void**)&wqch,g_wqc_h);cudaGetSymbolAddress((void**)&wqcl,g_wqc_l);
    cudaGetSymbolAddress((void**)&wqrh,g_wqr_h);cudaGetSymbolAddress((void**)&wqrl,g_wqr_l);
    cudaGetSymbolAddress((void**)&wkch,g_wkc_h);cudaGetSymbolAddress((void**)&wkcl,g_wkc_l);
    cudaGetSymbolAddress((void**)&wvh, g_wv_h); cudaGetSymbolAddress((void**)&wvl, g_wv_l);
    cudaGetSymbolAddress((void**)&woh, g_wo_h); cudaGetSymbolAddress((void**)&wol, g_wo_l);

    const int attn_smem = (DQK * 64 * 2 + 64 * DV + 64 * 64) * 4;
    cudaFuncSetAttribute(attn_kernel,
                         cudaFuncAttributeMaxDynamicSharedMemorySize, attn_smem);
    cudaFuncSetAttribute(mma_gemm,
                         cudaFuncAttributeMaxDynamicSharedMemorySize, MG_SMEM);

    dim3 blk(256);
    // input + weight splits
    split_f32<<<(TOKENS*HIDDEN/4 + 255)/256, blk>>>(x, xh, xl, TOKENS*HIDDEN/4);
    split_tr<<<dim3(1536/32, 2048/32), blk>>>(W_cp, wcph, wcpl, 2048, 1536);
    split_tr<<<dim3(512/32,  2048/32), blk>>>(W_c,  wch,  wcl,  2048, 512);
    split_tr<<<dim3(2048/32, 1536/32), blk>>>(W_qc, wqch, wqcl, 1536, 2048);
    split_tr<<<dim3(1024/32, 1536/32), blk>>>(W_qr, wqrh, wqrl, 1536, 1024);
    split_tr<<<dim3(2048/32, 512/32),  blk>>>(W_kc, wkch, wkcl, 512, 2048);
    split_tr<<<dim3(2048/32, 512/32),  blk>>>(W_v,  wvh,  wvl,  512, 2048);
    split_tr<<<dim3(2048/32, 2048/32), blk>>>(W_o,  woh,  wol,  2048, 2048);
    // latent projections (tensor cores)
    mma_gemm<<<dim3(1536/128, TOKENS/128), blk, MG_SMEM>>>(xh, xl, wcph, wcpl, cp, TOKENS, 1536, 2048);
    mma_gemm<<<dim3(512/128,  TOKENS/128), blk, MG_SMEM>>>(xh, xl, wch,  wcl,  c,  TOKENS, 512,  2048);
    kr_proj<<<TOKENS/4, blk>>>(x, W_kr, kr);
    // split latents
    split_f32<<<(TOKENS*1536/4 + 255)/256, blk>>>(cp, cph, cpl, TOKENS*1536/4);
    split_f32<<<(TOKENS*512/4  + 255)/256, blk>>>(c,  ch,  cl,  TOKENS*512/4);
    // q/k/v heads (tensor cores)
    mma_gemm<<<dim3(2048/128, TOKENS/128), blk, MG_SMEM>>>(cph, cpl, wqch, wqcl, qc, TOKENS, 2048, 1536);
    mma_gemm<<<dim3(1024/128, TOKENS/128), blk, MG_SMEM>>>(cph, cpl, wqrh, wqrl, qr, TOKENS, 1024, 1536);
    mma_gemm<<<dim3(2048/128, TOKENS/128), blk, MG_SMEM>>>(ch,  cl,  wkch, wkcl, kc, TOKENS, 2048, 512);
    mma_gemm<<<dim3(2048/128, TOKENS/128), blk, MG_SMEM>>>(ch,  cl,  wvh,  wvl,  vt, TOKENS, 2048, 512);
    // pack + rope
    pack_qk<<<dim3(S_/32, BH), blk>>>(qc, qr, NHEADS*DR, DR, Qt);
    pack_qk<<<dim3(S_/32, BH), blk>>>(kc, kr, DR, 0, Kt);
    pack_v <<<dim3(S_/64, BH), blk>>>(vt, V);
    // attention (fp32 for now)
    attn_kernel<<<dim3(S_/64, BH), blk, attn_smem>>>(Qt, Kt, V, attn);
    // output projection (tensor cores)
    split_f32<<<(TOKENS*2048/4 + 255)/256, blk>>>(attn, ah, al, TOKENS*2048/4);
    mma_gemm<<<dim3(2048/128, TOKENS/128), blk, MG_SMEM>>>(ah, al, woh, wol, out, TOKENS, 2048, 2048);
}

// round 8
// speedup vs baseline: 2.9543x; 1.9492x over previous
#include <cuda_runtime.h>
#include <cuda_bf16.h>
#include <math.h>
#include <stdint.h>

#define HIDDEN 2048
#define NHEADS 16
#define DK 128
#define DR 64
#define DV 128
#define DQK 192
#define B_ 2
#define S_ 2048
#define TOKENS (B_*S_)
#define BH (B_*NHEADS)

// ---------------- scratch (static device memory; allocation-free) ----------------
__device__ float g_c   [TOKENS*512];        // unused placeholder (kept small set)
__device__ float g_qc  [TOKENS*(NHEADS*DK)];
__device__ float g_qr  [TOKENS*(NHEADS*DR)];
__device__ float g_kc  [TOKENS*(NHEADS*DK)];
__device__ float g_kr  [TOKENS*DR];
__device__ float g_vt  [TOKENS*(NHEADS*DV)];

// bf16 hi/lo split activations
__device__ __align__(16) __nv_bfloat16 g_xh [TOKENS*HIDDEN];
__device__ __align__(16) __nv_bfloat16 g_xl [TOKENS*HIDDEN];
__device__ __align__(16) __nv_bfloat16 g_cph[TOKENS*1536];
__device__ __align__(16) __nv_bfloat16 g_cpl[TOKENS*1536];
__device__ __align__(16) __nv_bfloat16 g_ch [TOKENS*512];
__device__ __align__(16) __nv_bfloat16 g_cl [TOKENS*512];
__device__ __align__(16) __nv_bfloat16 g_ah [TOKENS*2048];
__device__ __align__(16) __nv_bfloat16 g_al [TOKENS*2048];
// attention operands, bf16 hi/lo
__device__ __align__(16) __nv_bfloat16 g_Qh [BH*S_*DQK], g_Ql [BH*S_*DQK];
__device__ __align__(16) __nv_bfloat16 g_Kh [BH*S_*DQK], g_Kl [BH*S_*DQK];
__device__ __align__(16) __nv_bfloat16 g_Vth[BH*DV*S_],  g_Vtl[BH*DV*S_];
// bf16 hi/lo transposed weights: Wt[N][K] = W[K][N]
__device__ __align__(16) __nv_bfloat16 g_wcp_h[1536*2048], g_wcp_l[1536*2048];
__device__ __align__(16) __nv_bfloat16 g_wc_h [512*2048],  g_wc_l [512*2048];
__device__ __align__(16) __nv_bfloat16 g_wqc_h[2048*1536], g_wqc_l[2048*1536];
__device__ __align__(16) __nv_bfloat16 g_wqr_h[1024*1536], g_wqr_l[1024*1536];
__device__ __align__(16) __nv_bfloat16 g_wkc_h[2048*512],  g_wkc_l[2048*512];
__device__ __align__(16) __nv_bfloat16 g_wv_h [2048*512],  g_wv_l [2048*512];
__device__ __align__(16) __nv_bfloat16 g_wo_h [2048*2048], g_wo_l [2048*2048];

// ======================= helpers (base sm_103 features only) ====================
__device__ __forceinline__ uint32_t smem_u32(const void* p) {
    return (uint32_t)__cvta_generic_to_shared(p);
}
__device__ __forceinline__ void ldsm4(uint32_t* r, uint32_t addr) {
    asm volatile("ldmatrix.sync.aligned.m8n8.x4.shared.b16 {%0,%1,%2,%3}, [%4];"
        : "=r"(r[0]), "=r"(r[1]), "=r"(r[2]), "=r"(r[3]) : "r"(addr));
}
__device__ __forceinline__ void mma16816(float* d, const uint32_t* a,
                                         uint32_t b0, uint32_t b1) {
    asm volatile("mma.sync.aligned.m16n8k16.row.col.f32.bf16.bf16.f32 "
        "{%0,%1,%2,%3}, {%4,%5,%6,%7}, {%8,%9}, {%0,%1,%2,%3};"
        : "+f"(d[0]), "+f"(d[1]), "+f"(d[2]), "+f"(d[3])
        : "r"(a[0]), "r"(a[1]), "r"(a[2]), "r"(a[3]), "r"(b0), "r"(b1));
}
// pack two fp32 -> bf16x2 (lo in low half)
__device__ __forceinline__ uint32_t pack2(float lo, float hi) {
    uint32_t r;
    asm("cvt.rn.bf16x2.f32 %0, %1, %2;" : "=r"(r) : "f"(hi), "f"(lo));
    return r;
}
__device__ __forceinline__ float bf16r(float x) {
    return __bfloat162float(__float2bfloat16(x));
}
__device__ __forceinline__ void cpa16(uint32_t dst, const void* src) {
    asm volatile("cp.async.cg.shared.global [%0], [%1], 16;" :: "r"(dst), "l"(src));
}
__device__ __forceinline__ void cpa_commit() {
    asm volatile("cp.async.commit_group;" ::: "memory");
}
__device__ __forceinline__ void cpa_wait0() {
    asm volatile("cp.async.wait_group 0;" ::: "memory");
}

// ======================= tensor-core GEMM: C[M,N] = A[M,K] @ Bt[N,K]^T ==========
// bf16x3: C += Ah*Bh + Ah*Bl + Al*Bh.  Optional bf16 hi/lo split output.
#define MG_SMEM 65536

__global__ void __launch_bounds__(256, 2) mma_gemm(
        const __nv_bfloat16* __restrict__ Ahg, const __nv_bfloat16* __restrict__ Alg,
        const __nv_bfloat16* __restrict__ Bhg, const __nv_bfloat16* __restrict__ Blg,
        float* __restrict__ C, __nv_bfloat16* __restrict__ Csh,
        __nv_bfloat16* __restrict__ Csl, int M, int N, int K)
{
    extern __shared__ char smem[];   // [Ah | Al | Bh | Bl], each 128 rows x 128B, SW128
    const uint32_t sb = smem_u32(smem);
    const int tid = threadIdx.x, wid = tid >> 5, lane = tid & 31;
    const int m0 = blockIdx.y * 128, n0 = blockIdx.x * 128;
    const int wm = (wid & 1) * 64;      // warp tile 64x32
    const int wn = (wid >> 1) * 32;

    float acc[16][4];
#pragma unroll
    for (int i = 0; i < 16; i++)
#pragma unroll
        for (int j = 0; j < 4; j++) acc[i][j] = 0.f;

    const int aRow  = lane & 15;
    const int aCsel = (lane >> 4) * 16;
    const int bRow  = (lane & 7) + ((lane >> 4) << 3);
    const int bCsel = ((lane >> 3) & 1) * 16;

    for (int k0 = 0; k0 < K; k0 += 64) {
        __syncthreads();
#pragma unroll
        for (int j = 0; j < 16; j++) {
            const int t = j >> 2;
            const int idx = (j & 3) * 256 + tid;
            const int r = idx >> 3, jc = idx & 7;
            const __nv_bfloat16* g = (t == 0) ? Ahg : (t == 1) ? Alg
                                   : (t == 2) ? Bhg : Blg;
            const int row = ((t < 2) ? m0 : n0) + r;
            const uint4 v = *(const uint4*)(g + (size_t)row * K + k0 + jc * 8);
            const uint32_t off = (uint32_t)(r * 128 + ((jc * 16) ^ ((r & 7) << 4)));
            *(uint4*)(smem + t * 16384 + off) = v;
        }
        __syncthreads();

        const uint32_t bAh = sb, bAl = sb + 16384, bBh = sb + 32768, bBl = sb + 49152;
#pragma unroll
        for (int ks = 0; ks < 4; ks++) {
            uint32_t ah[4][4], bh[2][4];
#pragma unroll
            for (int mt = 0; mt < 4; mt++) {
                const int r = wm + mt * 16 + aRow;
                const uint32_t off = r * 128 + ((ks * 32 + aCsel) ^ ((r & 7) << 4));
                ldsm4(ah[mt], bAh + off);
            }
#pragma unroll
            for (int np = 0; np < 2; np++) {
                const int r = wn + np * 16 + bRow;
                const uint32_t off = r * 128 + ((ks * 32 + bCsel) ^ ((r & 7) << 4));
                ldsm4(bh[np], bBh + off);
            }
#pragma unroll
            for (int mt = 0; mt < 4; mt++)
#pragma unroll
                for (int nt = 0; nt < 4; nt++)
                    mma16816(acc[mt * 4 + nt], ah[mt],
                             bh[nt >> 1][(nt & 1) * 2], bh[nt >> 1][(nt & 1) * 2 + 1]);
            {
                uint32_t bl[2][4];
#pragma unroll
                for (int np = 0; np < 2; np++) {
                    const int r = wn + np * 16 + bRow;
                    const uint32_t off = r * 128 + ((ks * 32 + bCsel) ^ ((r & 7) << 4));
                    ldsm4(bl[np], bBl + off);
                }
#pragma unroll
                for (int mt = 0; mt < 4; mt++)
#pragma unroll
                    for (int nt = 0; nt < 4; nt++)
                        mma16816(acc[mt * 4 + nt], ah[mt],
                                 bl[nt >> 1][(nt & 1) * 2], bl[nt >> 1][(nt & 1) * 2 + 1]);
            }
            {
                uint32_t al[4][4];
#pragma unroll
                for (int mt = 0; mt < 4; mt++) {
                    const int r = wm + mt * 16 + aRow;
                    const uint32_t off = r * 128 + ((ks * 32 + aCsel) ^ ((r & 7) << 4));
                    ldsm4(al[mt], bAl + off);
                }
#pragma unroll
                for (int mt = 0; mt < 4; mt++)
#pragma unroll
                    for (int nt = 0; nt < 4; nt++)
                        mma16816(acc[mt * 4 + nt], al[mt],
                                 bh[nt >> 1][(nt & 1) * 2], bh[nt >> 1][(nt & 1) * 2 + 1]);
            }
        }
    }

    const int er = lane >> 2, ec = (lane & 3) * 2;
    if (Csh) {
        // bf16 hi/lo split output
        uint32_t* oh = (uint32_t*)Csh;
        uint32_t* ol = (uint32_t*)Csl;
#pragma unroll
        for (int mt = 0; mt < 4; mt++)
#pragma unroll
            for (int nt = 0; nt < 4; nt++) {
                const int row = m0 + wm + mt * 16 + er;
                const int col = n0 + wn + nt * 8 + ec;
                const uint32_t i0 = ((uint32_t)row * N + col) >> 1;
                const uint32_t i1 = i0 + 4u * N;
                float a0 = acc[mt*4+nt][0], a1 = acc[mt*4+nt][1];
                float a2 = acc[mt*4+nt][2], a3 = acc[mt*4+nt][3];
                oh[i0] = pack2(a0, a1);
                ol[i0] = pack2(a0 - bf16r(a0), a1 - bf16r(a1));
                oh[i1] = pack2(a2, a3);
                ol[i1] = pack2(a2 - bf16r(a2), a3 - bf16r(a3));
            }
    } else {
#pragma unroll
        for (int mt = 0; mt < 4; mt++)
#pragma unroll
            for (int nt = 0; nt < 4; nt++) {
                const int row = m0 + wm + mt * 16 + er;
                const int col = n0 + wn + nt * 8 + ec;
                float* cp = C + (size_t)row * N + col;
                *(float2*)cp = make_float2(acc[mt*4+nt][0], acc[mt*4+nt][1]);
                *(float2*)(cp + (size_t)8 * N) = make_float2(acc[mt*4+nt][2], acc[mt*4+nt][3]);
            }
    }
}

// ---------------- fp32 -> bf16 hi/lo split (elementwise) -----------------------
__global__ void __launch_bounds__(256) split_f32(const float* __restrict__ in,
        __nv_bfloat16* __restrict__ hi, __nv_bfloat16* __restrict__ lo, int n4)
{
    const int i = blockIdx.x * 256 + threadIdx.x;
    if (i >= n4) return;
    const float4 v = ((const float4*)in)[i];
    float xs[4] = {v.x, v.y, v.z, v.w};
    union { __nv_bfloat16 b[4]; uint2 u; } H, L;
#pragma unroll
    for (int j = 0; j < 4; j++) {
        __nv_bfloat16 h = __float2bfloat16(xs[j]);
        H.b[j] = h;
        L.b[j] = __float2bfloat16(xs[j] - __bfloat162float(h));
    }
    ((uint2*)hi)[i] = H.u;
    ((uint2*)lo)[i] = L.u;
}

// ---------------- fp32 W[K,N] -> bf16 hi/lo Wt[N,K] (transpose split) ----------
__global__ void __launch_bounds__(256) split_tr(const float* __restrict__ W,
        __nv_bfloat16* __restrict__ hi, __nv_bfloat16* __restrict__ lo, int K, int N)
{
    __shared__ float t[32][33];
    const int n0 = blockIdx.x * 32, k0 = blockIdx.y * 32;
    const int tx = threadIdx.x & 31, ty = threadIdx.x >> 5;
#pragma unroll
    for (int rr = 0; rr < 32; rr += 8)
        t[ty + rr][tx] = W[(size_t)(k0 + ty + rr) * N + n0 + tx];
    __syncthreads();
#pragma unroll
    for (int rr = 0; rr < 32; rr += 8) {
        const float x = t[tx][ty + rr];
        const __nv_bfloat16 h = __float2bfloat16(x);
        const size_t o = (size_t)(n0 + ty + rr) * K + k0 + tx;
        hi[o] = h;
        lo[o] = __float2bfloat16(x - __bfloat162float(h));
    }
}

// ---------------- skinny projection: out[tok,64] = x[tok,2048] @ Wkr[2048,64] ----
__global__ void __launch_bounds__(256) kr_proj(const float* __restrict__ x,
        const float* __restrict__ Wkr, float* __restrict__ out)
{
    __shared__ float sx[4][HIDDEN];
    const int t0 = blockIdx.x * 4;
    for (int f = threadIdx.x; f < 4 * HIDDEN / 4; f += 256) {
        int row = f >> 9, c4 = f & 511;
        ((float4*)sx[row])[c4] = ((const float4*)(x + (size_t)(t0 + row) * HIDDEN))[c4];
    }
    __syncthreads();
    const int n = threadIdx.x & 63, tl = threadIdx.x >> 6;
    float s = 0.f;
#pragma unroll 8
    for (int k = 0; k < HIDDEN; k++) s += sx[tl][k] * Wkr[k * 64 + n];
    out[(size_t)(t0 + tl) * 64 + n] = s;
}

// ---------------- pack q/k -> bf16 hi/lo, row-major [bh][s][192] ----------------
__global__ void __launch_bounds__(256) pack_qk_bf16(const float* __restrict__ cbuf,
        const float* __restrict__ rbuf, int rRowStride, int rHeadStride,
        __nv_bfloat16* __restrict__ Oh, __nv_bfloat16* __restrict__ Ol)
{
    __shared__ float sinv[32];
    const int bh = blockIdx.y, b = bh >> 4, h = bh & 15;
    const int s0 = blockIdx.x * 32;
    if (threadIdx.x < 32)
        sinv[threadIdx.x] = (float)pow(10000.0, -(double)threadIdx.x / 32.0);
    __syncthreads();
    uint32_t* oh = (uint32_t*)Oh;
    uint32_t* ol = (uint32_t*)Ol;
    for (int f = threadIdx.x; f < 32 * 96; f += 256) {
        const int row = f / 96, dp = f % 96, d = dp * 2;
        const size_t tok = (size_t)b * S_ + s0 + row;
        float v0, v1;
        if (d < 128) {
            const float* cp = cbuf + tok * 2048 + h * 128 + d;
            v0 = cp[0]; v1 = cp[1];
        } else {
            const int dd = d - 128, i = dd >> 1;
            const float* rp = rbuf + tok * rRowStride + h * rHeadStride;
            const float re = rp[2 * i], im = rp[2 * i + 1];
            const float ang = (float)(s0 + row) * sinv[i];
            const float cs = cosf(ang), sn = sinf(ang);
            v0 = re * cs - im * sn;
            v1 = re * sn + im * cs;
        }
        const size_t idx = ((size_t)bh * S_ + s0 + row) * 96 + dp;
        oh[idx] = pack2(v0, v1);
        ol[idx] = pack2(v0 - bf16r(v0), v1 - bf16r(v1));
    }
}

// ---------------- pack v -> bf16 hi/lo transposed [bh][d][s] -------------------
__global__ void __launch_bounds__(256) pack_vt_bf16(const float* __restrict__ vt,
        __nv_bfloat16* __restrict__ Vth, __nv_bfloat16* __restrict__ Vtl)
{
    __shared__ float t[64][33];
    const int bh = blockIdx.y, b = bh >> 4, h = bh & 15;
    const int s0 = blockIdx.x * 64, d0 = blockIdx.z * 32;
    for (int f = threadIdx.x; f < 64 * 32; f += 256) {
        const int si = f >> 5, di = f & 31;
        t[si][di] = vt[(size_t)(b * S_ + s0 + si) * 2048 + h * 128 + d0 + di];
    }
    __syncthreads();
    uint32_t* oh = (uint32_t*)Vth;
    uint32_t* ol = (uint32_t*)Vtl;
    for (int f = threadIdx.x; f < 32 * 32; f += 256) {
        const int di = f >> 5, sp = f & 31;
        const float v0 = t[2 * sp][di], v1 = t[2 * sp + 1][di];
        const size_t idx = ((size_t)(bh * 128) + d0 + di) * 1024 + (s0 >> 1) + sp;
        oh[idx] = pack2(v0, v1);
        ol[idx] = pack2(v0 - bf16r(v0), v1 - bf16r(v1));
    }
}

// ---------------- tensor-core causal flash attention ---------------------------
// Q,K: bf16 hi/lo [bh][s][192]; Vt: bf16 hi/lo [bh][d=128][s]
// Output: bf16 hi/lo [tok][h*128+d]  (feeds the W_o GEMM directly)
// CTA: 64 q-rows, 128 threads (4 warps x 16 rows), 64-wide k-tiles.
#define AQ_STRIDE 400      // bytes per q/k smem row (192*2 padded to 200 el)
#define AV_STRIDE 144      // bytes per v smem row (64*2 padded to 72 el)
#define A_QH 0
#define A_QL 25600
#define A_KH 51200
#define A_KL 76800
#define A_VH 102400
#define A_VL 120832
#define ATTN_SMEM 139264

__global__ void __launch_bounds__(128, 1) attn_tc(
        const __nv_bfloat16* __restrict__ Qhg, const __nv_bfloat16* __restrict__ Qlg,
        const __nv_bfloat16* __restrict__ Khg, const __nv_bfloat16* __restrict__ Klg,
        const __nv_bfloat16* __restrict__ Vhg, const __nv_bfloat16* __restrict__ Vlg,
        __nv_bfloat16* __restrict__ Ohg, __nv_bfloat16* __restrict__ Olg)
{
    extern __shared__ char smem[];
    const uint32_t sb = smem_u32(smem);
    const int tid = threadIdx.x, wid = tid >> 5, lane = tid & 31;
    const int bh = blockIdx.y, b = bh >> 4, h = bh & 15;
    const int qt = gridDim.x - 1 - blockIdx.x;
    const int q0 = qt * 64;

    // ldmatrix geometry
    const int er = lane >> 2, ec = (lane & 3) * 2;
    const int aRow = lane & 15, aSel = (lane >> 4) * 16;
    const int bRow = (lane & 7) + ((lane >> 4) << 3), bSel = ((lane >> 3) & 1) * 16;
    const uint32_t qh_base = sb + A_QH + (wid * 16 + aRow) * AQ_STRIDE + aSel;
    const uint32_t ql_base = sb + A_QL + (wid * 16 + aRow) * AQ_STRIDE + aSel;
    const uint32_t kh_base = sb + A_KH + bRow * AQ_STRIDE + bSel;
    const uint32_t kl_base = sb + A_KL + bRow * AQ_STRIDE + bSel;
    const uint32_t vh_base = sb + A_VH + bRow * AV_STRIDE + bSel;
    const uint32_t vl_base = sb + A_VL + bRow * AV_STRIDE + bSel;

    // load Q tile once (64 rows x 192 el, hi+lo): 1536 x 16B each
    for (int f = tid; f < 1536; f += 128) {
        const int r = f / 24, j = f % 24;
        const size_t src = (size_t)(bh * S_ + q0 + r) * 192 + j * 8;
        cpa16(sb + A_QH + r * AQ_STRIDE + j * 16, Qhg + src);
        cpa16(sb + A_QL + r * AQ_STRIDE + j * 16, Qlg + src);
    }
    cpa_commit();

    float oacc[16][4];
#pragma unroll
    for (int i = 0; i < 16; i++)
#pragma unroll
        for (int j = 0; j < 4; j++) oacc[i][j] = 0.f;
    float m0 = -1e30f, m1 = -1e30f, l0 = 0.f, l1 = 0.f;

    const float cst = 0.0721687836487032f * 1.44269504088896f;  // 1/sqrt(192)*log2e
    const int lrow0 = wid * 16 + er, lrow1 = lrow0 + 8;

    for (int kt = 0; kt <= qt; kt++) {
        const int k0 = kt * 64;
        // stage K (64x192 hi/lo) and V (128x64 hi/lo)
        for (int f = tid; f < 1536; f += 128) {
            const int r = f / 24, j = f % 24;
            const size_t src = (size_t)(bh * S_ + k0 + r) * 192 + j * 8;
            cpa16(sb + A_KH + r * AQ_STRIDE + j * 16, Khg + src);
            cpa16(sb + A_KL + r * AQ_STRIDE + j * 16, Klg + src);
        }
        for (int f = tid; f < 1024; f += 128) {
            const int d = f >> 3, j = f & 7;
            const size_t src = (size_t)(bh * 128 + d) * 2048 + k0 + j * 8;
            cpa16(sb + A_VH + d * AV_STRIDE + j * 16, Vhg + src);
            cpa16(sb + A_VL + d * AV_STRIDE + j * 16, Vlg + src);
        }
        cpa_commit();
        cpa_wait0();
        __syncthreads();

        // ---- S = Q K^T (bf16x3) ----
        float sacc[8][4];
#pragma unroll
        for (int i = 0; i < 8; i++)
#pragma unroll
            for (int j = 0; j < 4; j++) sacc[i][j] = 0.f;
#pragma unroll
        for (int ks = 0; ks < 12; ks++) {
            uint32_t ah[4], al4[4];
            ldsm4(ah, qh_base + ks * 32);
            ldsm4(al4, ql_base + ks * 32);
#pragma unroll
            for (int np = 0; np < 4; np++) {
                uint32_t bh4[4], bl4[4];
                ldsm4(bh4, kh_base + np * (16 * AQ_STRIDE) + ks * 32);
                mma16816(sacc[np*2],   ah,  bh4[0], bh4[1]);
                mma16816(sacc[np*2+1], ah,  bh4[2], bh4[3]);
                mma16816(sacc[np*2],   al4, bh4[0], bh4[1]);
                mma16816(sacc[np*2+1], al4, bh4[2], bh4[3]);
                ldsm4(bl4, kl_base + np * (16 * AQ_STRIDE) + ks * 32);
                mma16816(sacc[np*2],   ah,  bl4[0], bl4[1]);
                mma16816(sacc[np*2+1], ah,  bl4[2], bl4[3]);
            }
        }

        // ---- online softmax (base-2) ----
        const bool diag = (kt == qt);
        float mx0 = -1e30f, mx1 = -1e30f;
#pragma unroll
        for (int nt = 0; nt < 8; nt++) {
            const int colb = nt * 8 + ec;
#pragma unroll
            for (int j = 0; j < 2; j++) {
                float v = sacc[nt][j] * cst;
                if (diag && (colb + j) > lrow0) v = -1e30f;
                sacc[nt][j] = v;
                mx0 = fmaxf(mx0, v);
            }
#pragma unroll
            for (int j = 2; j < 4; j++) {
                float v = sacc[nt][j] * cst;
                if (diag && (colb + j - 2) > lrow1) v = -1e30f;
                sacc[nt][j] = v;
                mx1 = fmaxf(mx1, v);
            }
        }
        mx0 = fmaxf(mx0, __shfl_xor_sync(0xffffffffu, mx0, 1));
        mx0 = fmaxf(mx0, __shfl_xor_sync(0xffffffffu, mx0, 2));
        mx1 = fmaxf(mx1, __shfl_xor_sync(0xffffffffu, mx1, 1));
        mx1 = fmaxf(mx1, __shfl_xor_sync(0xffffffffu, mx1, 2));
        const float nm0 = fmaxf(m0, mx0), nm1 = fmaxf(m1, mx1);
        const float c0 = exp2f(m0 - nm0), c1 = exp2f(m1 - nm1);
        m0 = nm0; m1 = nm1;
        float rs0 = 0.f, rs1 = 0.f;
#pragma unroll
        for (int nt = 0; nt < 8; nt++) {
            sacc[nt][0] = exp2f(sacc[nt][0] - nm0);
            sacc[nt][1] = exp2f(sacc[nt][1] - nm0);
            sacc[nt][2] = exp2f(sacc[nt][2] - nm1);
            sacc[nt][3] = exp2f(sacc[nt][3] - nm1);
            rs0 += sacc[nt][0] + sacc[nt][1];
            rs1 += sacc[nt][2] + sacc[nt][3];
        }
        rs0 += __shfl_xor_sync(0xffffffffu, rs0, 1);
        rs0 += __shfl_xor_sync(0xffffffffu, rs0, 2);
        rs1 += __shfl_xor_sync(0xffffffffu, rs1, 1);
        rs1 += __shfl_xor_sync(0xffffffffu, rs1, 2);
        l0 = l0 * c0 + rs0;
        l1 = l1 * c1 + rs1;
#pragma unroll
        for (int i = 0; i < 16; i++) {
            oacc[i][0] *= c0; oacc[i][1] *= c0;
            oacc[i][2] *= c1; oacc[i][3] *= c1;
        }

        // ---- O += P V (bf16x3: PhVh + PlVh + PhVl) ----
#pragma unroll
        for (int ks2 = 0; ks2 < 4; ks2++) {
            const float* s0 = sacc[2 * ks2];
            const float* s1 = sacc[2 * ks2 + 1];
            uint32_t pa[4], pl[4];
            pa[0] = pack2(s0[0], s0[1]);
            pa[1] = pack2(s0[2], s0[3]);
            pa[2] = pack2(s1[0], s1[1]);
            pa[3] = pack2(s1[2], s1[3]);
            pl[0] = pack2(s0[0] - bf16r(s0[0]), s0[1] - bf16r(s0[1]));
            pl[1] = pack2(s0[2] - bf16r(s0[2]), s0[3] - bf16r(s0[3]));
            pl[2] = pack2(s1[0] - bf16r(s1[0]), s1[1] - bf16r(s1[1]));
            pl[3] = pack2(s1[2] - bf16r(s1[2]), s1[3] - bf16r(s1[3]));
#pragma unroll
            for (int np = 0; np < 8; np++) {
                uint32_t vh4[4], vl4[4];
                ldsm4(vh4, vh_base + np * (16 * AV_STRIDE) + ks2 * 32);
                mma16816(oacc[np*2],   pa, vh4[0], vh4[1]);
                mma16816(oacc[np*2+1], pa, vh4[2], vh4[3]);
                mma16816(oacc[np*2],   pl, vh4[0], vh4[1]);
                mma16816(oacc[np*2+1], pl, vh4[2], vh4[3]);
                ldsm4(vl4, vl_base + np * (16 * AV_STRIDE) + ks2 * 32);
                mma16816(oacc[np*2],   pa, vl4[0], vl4[1]);
                mma16816(oacc[np*2+1], pa, vl4[2], vl4[3]);
            }
        }
        __syncthreads();
    }

    // ---- epilogue: normalize, split to bf16 hi/lo, write [tok][h*128+d] --------
    const float i0 = 1.f / l0, i1 = 1.f / l1;
    const int row0 = q0 + wid * 16 + er;
    uint32_t* oh = (uint32_t*)Ohg;
    uint32_t* ol = (uint32_t*)Olg;
#pragma unroll
    for (int nt = 0; nt < 16; nt++) {
        const int col = nt * 8 + ec;
        const float v00 = oacc[nt][0] * i0, v01 = oacc[nt][1] * i0;
        const float v10 = oacc[nt][2] * i1, v11 = oacc[nt][3] * i1;
        const size_t o0 = (((size_t)(b * S_ + row0)) * 2048 + h * 128 + col) >> 1;
        const size_t o1 = (((size_t)(b * S_ + row0 + 8)) * 2048 + h * 128 + col) >> 1;
        oh[o0] = pack2(v00, v01);
        ol[o0] = pack2(v00 - bf16r(v00), v01 - bf16r(v01));
        oh[o1] = pack2(v10, v11);
        ol[o1] = pack2(v10 - bf16r(v10), v11 - bf16r(v11));
    }
}

// ---------------- orchestration -------------------------------------------------
extern "C" void kernel_launch(void* const* d_in, const int* in_sizes, int n_in,
                              void* d_out, int out_size)
{
    const float* x    = (const float*)d_in[0];
    const float* W_c  = (const float*)d_in[1];
    const float* W_cp = (const float*)d_in[2];
    const float* W_qc = (const float*)d_in[3];
    const float* W_qr = (const float*)d_in[4];
    const float* W_kc = (const float*)d_in[5];
    const float* W_kr = (const float*)d_in[6];
    const float* W_v  = (const float*)d_in[7];
    const float* W_o  = (const float*)d_in[8];
    float* out = (float*)d_out;

    float *qc, *qr, *kc, *kr, *vt;
    cudaGetSymbolAddress((void**)&qc,   g_qc);
    cudaGetSymbolAddress((void**)&qr,   g_qr);
    cudaGetSymbolAddress((void**)&kc,   g_kc);
    cudaGetSymbolAddress((void**)&kr,   g_kr);
    cudaGetSymbolAddress((void**)&vt,   g_vt);

    __nv_bfloat16 *xh,*xl,*cph,*cpl,*ch,*cl,*ah,*al;
    __nv_bfloat16 *Qh,*Ql,*Kh,*Kl,*Vth,*Vtl;
    __nv_bfloat16 *wcph,*wcpl,*wch,*wcl,*wqch,*wqcl,*wqrh,*wqrl,*wkch,*wkcl,*wvh,*wvl,*woh,*wol;
    cudaGetSymbolAddress((void**)&xh,  g_xh);   cudaGetSymbolAddress((void**)&xl,  g_xl);
    cudaGetSymbolAddress((void**)&cph, g_cph);  cudaGetSymbolAddress((void**)&cpl, g_cpl);
    cudaGetSymbolAddress((void**)&ch,  g_ch);   cudaGetSymbolAddress((void**)&cl,  g_cl);
    cudaGetSymbolAddress((void**)&ah,  g_ah);   cudaGetSymbolAddress((void**)&al,  g_al);
    cudaGetSymbolAddress((void**)&Qh,  g_Qh);   cudaGetSymbolAddress((void**)&Ql,  g_Ql);
    cudaGetSymbolAddress((void**)&Kh,  g_Kh);   cudaGetSymbolAddress((void**)&Kl,  g_Kl);
    cudaGetSymbolAddress((void**)&Vth, g_Vth);  cudaGetSymbolAddress((void**)&Vtl, g_Vtl);
    cudaGetSymbolAddress((void**)&wcph,g_wcp_h);cudaGetSymbolAddress((void**)&wcpl,g_wcp_l);
    cudaGetSymbolAddress((void**)&wch, g_wc_h); cudaGetSymbolAddress((void**)&wcl, g_wc_l);
    cudaGetSymbolAddress((void**)&wqch,g_wqc_h);cudaGetSymbolAddress((void**)&wqcl,g_wqc_l);
    cudaGetSymbolAddress((void**)&wqrh,g_wqr_h);cudaGetSymbolAddress((void**)&wqrl,g_wqr_l);
    cudaGetSymbolAddress((void**)&wkch,g_wkc_h);cudaGetSymbolAddress((void**)&wkcl,g_wkc_l);
    cudaGetSymbolAddress((void**)&wvh, g_wv_h); cudaGetSymbolAddress((void**)&wvl, g_wv_l);
    cudaGetSymbolAddress((void**)&woh, g_wo_h); cudaGetSymbolAddress((void**)&wol, g_wo_l);

    cudaFuncSetAttribute(mma_gemm,
                         cudaFuncAttributeMaxDynamicSharedMemorySize, MG_SMEM);
    cudaFuncSetAttribute(attn_tc,
                         cudaFuncAttributeMaxDynamicSharedMemorySize, ATTN_SMEM);

    dim3 blk(256);
    // input + weight splits
    split_f32<<<(TOKENS*HIDDEN/4 + 255)/256, blk>>>(x, xh, xl, TOKENS*HIDDEN/4);
    split_tr<<<dim3(1536/32, 2048/32), blk>>>(W_cp, wcph, wcpl, 2048, 1536);
    split_tr<<<dim3(512/32,  2048/32), blk>>>(W_c,  wch,  wcl,  2048, 512);
    split_tr<<<dim3(2048/32, 1536/32), blk>>>(W_qc, wqch, wqcl, 1536, 2048);
    split_tr<<<dim3(1024/32, 1536/32), blk>>>(W_qr, wqrh, wqrl, 1536, 1024);
    split_tr<<<dim3(2048/32, 512/32),  blk>>>(W_kc, wkch, wkcl, 512, 2048);
    split_tr<<<dim3(2048/32, 512/32),  blk>>>(W_v,  wvh,  wvl,  512, 2048);
    split_tr<<<dim3(2048/32, 2048/32), blk>>>(W_o,  woh,  wol,  2048, 2048);
    // latent projections (split bf16 output — skips split_f32 passes)
    mma_gemm<<<dim3(1536/128, TOKENS/128), blk, MG_SMEM>>>(xh, xl, wcph, wcpl,
        nullptr, cph, cpl, TOKENS, 1536, 2048);
    mma_gemm<<<dim3(512/128,  TOKENS/128), blk, MG_SMEM>>>(xh, xl, wch, wcl,
        nullptr, ch, cl, TOKENS, 512, 2048);
    kr_proj<<<TOKENS/4, blk>>>(x, W_kr, kr);
    // q/k/v heads (fp32 out, consumed by pack kernels)
    mma_gemm<<<dim3(2048/128, TOKENS/128), blk, MG_SMEM>>>(cph, cpl, wqch, wqcl,
        qc, nullptr, nullptr, TOKENS, 2048, 1536);
    mma_gemm<<<dim3(1024/128, TOKENS/128), blk, MG_SMEM>>>(cph, cpl, wqrh, wqrl,
        qr, nullptr, nullptr, TOKENS, 1024, 1536);
    mma_gemm<<<dim3(2048/128, TOKENS/128), blk, MG_SMEM>>>(ch, cl, wkch, wkcl,
        kc, nullptr, nullptr, TOKENS, 2048, 512);
    mma_gemm<<<dim3(2048/128, TOKENS/128), blk, MG_SMEM>>>(ch, cl, wvh, wvl,
        vt, nullptr, nullptr, TOKENS, 2048, 512);
    // pack + rope -> bf16 hi/lo attention operands
    pack_qk_bf16<<<dim3(S_/32, BH), blk>>>(qc, qr, NHEADS*DR, DR, Qh, Ql);
    pack_qk_bf16<<<dim3(S_/32, BH), blk>>>(kc, kr, DR, 0, Kh, Kl);
    pack_vt_bf16<<<dim3(S_/64, BH, 4), blk>>>(vt, Vth, Vtl);
    // tensor-core causal flash attention (writes ah/al bf16 hi/lo directly)
    attn_tc<<<dim3(S_/64, BH), dim3(128), ATTN_SMEM>>>(Qh, Ql, Kh, Kl, Vth, Vtl, ah, al);
    // output projection
    mma_gemm<<<dim3(2048/128, TOKENS/128), blk, MG_SMEM>>>(ah, al, woh, wol,
        out, nullptr, nullptr, TOKENS, 2048, 2048);
}

// round 17
// speedup vs baseline: 3.2462x; 1.0988x over previous
#include <cuda_runtime.h>
#include <cuda_bf16.h>
#include <math.h>
#include <stdint.h>

#define HIDDEN 2048
#define NHEADS 16
#define DK 128
#define DR 64
#define DV 128
#define DQK 192
#define B_ 2
#define S_ 2048
#define TOKENS (B_*S_)
#define BH (B_*NHEADS)

// ---------------- scratch (static device memory; allocation-free) ----------------
__device__ float g_qc  [TOKENS*(NHEADS*DK)];
__device__ float g_qr  [TOKENS*(NHEADS*DR)];
__device__ float g_kc  [TOKENS*(NHEADS*DK)];
__device__ float g_kr  [TOKENS*DR];
__device__ float g_vt  [TOKENS*(NHEADS*DV)];

// bf16 hi/lo split activations
__device__ __align__(16) __nv_bfloat16 g_xh [TOKENS*HIDDEN];
__device__ __align__(16) __nv_bfloat16 g_xl [TOKENS*HIDDEN];
__device__ __align__(16) __nv_bfloat16 g_cph[TOKENS*1536];
__device__ __align__(16) __nv_bfloat16 g_cpl[TOKENS*1536];
__device__ __align__(16) __nv_bfloat16 g_ch [TOKENS*512];
__device__ __align__(16) __nv_bfloat16 g_cl [TOKENS*512];
__device__ __align__(16) __nv_bfloat16 g_ah [TOKENS*2048];
__device__ __align__(16) __nv_bfloat16 g_al [TOKENS*2048];
// attention operands, bf16 hi/lo
__device__ __align__(16) __nv_bfloat16 g_Qh [BH*S_*DQK], g_Ql [BH*S_*DQK];
__device__ __align__(16) __nv_bfloat16 g_Kh [BH*S_*DQK], g_Kl [BH*S_*DQK];
__device__ __align__(16) __nv_bfloat16 g_Vth[BH*DV*S_],  g_Vtl[BH*DV*S_];
// bf16 hi/lo transposed weights: Wt[N][K] = W[K][N]
__device__ __align__(16) __nv_bfloat16 g_wcp_h[1536*2048], g_wcp_l[1536*2048];
__device__ __align__(16) __nv_bfloat16 g_wc_h [512*2048],  g_wc_l [512*2048];
__device__ __align__(16) __nv_bfloat16 g_wqc_h[2048*1536], g_wqc_l[2048*1536];
__device__ __align__(16) __nv_bfloat16 g_wqr_h[1024*1536], g_wqr_l[1024*1536];
__device__ __align__(16) __nv_bfloat16 g_wkc_h[2048*512],  g_wkc_l[2048*512];
__device__ __align__(16) __nv_bfloat16 g_wv_h [2048*512],  g_wv_l [2048*512];
__device__ __align__(16) __nv_bfloat16 g_wo_h [2048*2048], g_wo_l [2048*2048];

// ======================= helpers (base sm_103 features only) ====================
__device__ __forceinline__ uint32_t smem_u32(const void* p) {
    return (uint32_t)__cvta_generic_to_shared(p);
}
__device__ __forceinline__ void ldsm4(uint32_t* r, uint32_t addr) {
    asm volatile("ldmatrix.sync.aligned.m8n8.x4.shared.b16 {%0,%1,%2,%3}, [%4];"
        : "=r"(r[0]), "=r"(r[1]), "=r"(r[2]), "=r"(r[3]) : "r"(addr));
}
__device__ __forceinline__ void mma16816(float* d, const uint32_t* a,
                                         uint32_t b0, uint32_t b1) {
    asm volatile("mma.sync.aligned.m16n8k16.row.col.f32.bf16.bf16.f32 "
        "{%0,%1,%2,%3}, {%4,%5,%6,%7}, {%8,%9}, {%0,%1,%2,%3};"
        : "+f"(d[0]), "+f"(d[1]), "+f"(d[2]), "+f"(d[3])
        : "r"(a[0]), "r"(a[1]), "r"(a[2]), "r"(a[3]), "r"(b0), "r"(b1));
}
__device__ __forceinline__ uint32_t pack2(float lo, float hi) {
    uint32_t r;
    asm("cvt.rn.bf16x2.f32 %0, %1, %2;" : "=r"(r) : "f"(hi), "f"(lo));
    return r;
}
__device__ __forceinline__ float bf16r(float x) {
    return __bfloat162float(__float2bfloat16(x));
}
__device__ __forceinline__ void cpa16(uint32_t dst, const void* src) {
    asm volatile("cp.async.cg.shared.global [%0], [%1], 16;" :: "r"(dst), "l"(src));
}
__device__ __forceinline__ void cpa_commit() {
    asm volatile("cp.async.commit_group;" ::: "memory");
}
__device__ __forceinline__ void cpa_wait0() {
    asm volatile("cp.async.wait_group 0;" ::: "memory");
}
__device__ __forceinline__ void cpa_wait1() {
    asm volatile("cp.async.wait_group 1;" ::: "memory");
}

// ======================= tensor-core GEMM: C[M,N] = A[M,K] @ Bt[N,K]^T ==========
// bf16x3: C += Ah*Bh + Ah*Bl + Al*Bh.  Optional bf16 hi/lo split output.
#define MG_SMEM 65536

__global__ void __launch_bounds__(256, 2) mma_gemm(
        const __nv_bfloat16* __restrict__ Ahg, const __nv_bfloat16* __restrict__ Alg,
        const __nv_bfloat16* __restrict__ Bhg, const __nv_bfloat16* __restrict__ Blg,
        float* __restrict__ C, __nv_bfloat16* __restrict__ Csh,
        __nv_bfloat16* __restrict__ Csl, int M, int N, int K)
{
    extern __shared__ char smem[];   // [Ah | Al | Bh | Bl], each 128 rows x 128B, SW128
    const uint32_t sb = smem_u32(smem);
    const int tid = threadIdx.x, wid = tid >> 5, lane = tid & 31;
    const int m0 = blockIdx.y * 128, n0 = blockIdx.x * 128;
    const int wm = (wid & 1) * 64;      // warp tile 64x32
    const int wn = (wid >> 1) * 32;

    float acc[16][4];
#pragma unroll
    for (int i = 0; i < 16; i++)
#pragma unroll
        for (int j = 0; j < 4; j++) acc[i][j] = 0.f;

    const int aRow  = lane & 15;
    const int aCsel = (lane >> 4) * 16;
    const int bRow  = (lane & 7) + ((lane >> 4) << 3);
    const int bCsel = ((lane >> 3) & 1) * 16;

    for (int k0 = 0; k0 < K; k0 += 64) {
        __syncthreads();
        // ---- stage 4 tiles via cp.async (16 x 16B per thread) ----
#pragma unroll
        for (int j = 0; j < 16; j++) {
            const int t = j >> 2;
            const int idx = (j & 3) * 256 + tid;
            const int r = idx >> 3, jc = idx & 7;
            const __nv_bfloat16* g = (t == 0) ? Ahg : (t == 1) ? Alg
                                   : (t == 2) ? Bhg : Blg;
            const int row = ((t < 2) ? m0 : n0) + r;
            const uint32_t off = (uint32_t)(r * 128 + ((jc * 16) ^ ((r & 7) << 4)));
            cpa16(sb + t * 16384 + off, g + (size_t)row * K + k0 + jc * 8);
        }
        cpa_commit();
        cpa_wait0();
        __syncthreads();

        const uint32_t bAh = sb, bAl = sb + 16384, bBh = sb + 32768, bBl = sb + 49152;
#pragma unroll
        for (int ks = 0; ks < 4; ks++) {
            uint32_t ah[4][4], bh[2][4];
#pragma unroll
            for (int mt = 0; mt < 4; mt++) {
                const int r = wm + mt * 16 + aRow;
                const uint32_t off = r * 128 + ((ks * 32 + aCsel) ^ ((r & 7) << 4));
                ldsm4(ah[mt], bAh + off);
            }
#pragma unroll
            for (int np = 0; np < 2; np++) {
                const int r = wn + np * 16 + bRow;
                const uint32_t off = r * 128 + ((ks * 32 + bCsel) ^ ((r & 7) << 4));
                ldsm4(bh[np], bBh + off);
            }
#pragma unroll
            for (int mt = 0; mt < 4; mt++)
#pragma unroll
                for (int nt = 0; nt < 4; nt++)
                    mma16816(acc[mt * 4 + nt], ah[mt],
                             bh[nt >> 1][(nt & 1) * 2], bh[nt >> 1][(nt & 1) * 2 + 1]);
            {
                uint32_t bl[2][4];
#pragma unroll
                for (int np = 0; np < 2; np++) {
                    const int r = wn + np * 16 + bRow;
                    const uint32_t off = r * 128 + ((ks * 32 + bCsel) ^ ((r & 7) << 4));
                    ldsm4(bl[np], bBl + off);
                }
#pragma unroll
                for (int mt = 0; mt < 4; mt++)
#pragma unroll
                    for (int nt = 0; nt < 4; nt++)
                        mma16816(acc[mt * 4 + nt], ah[mt],
                                 bl[nt >> 1][(nt & 1) * 2], bl[nt >> 1][(nt & 1) * 2 + 1]);
            }
            {
                uint32_t al[4][4];
#pragma unroll
                for (int mt = 0; mt < 4; mt++) {
                    const int r = wm + mt * 16 + aRow;
                    const uint32_t off = r * 128 + ((ks * 32 + aCsel) ^ ((r & 7) << 4));
                    ldsm4(al[mt], bAl + off);
                }
#pragma unroll
                for (int mt = 0; mt < 4; mt++)
#pragma unroll
                    for (int nt = 0; nt < 4; nt++)
                        mma16816(acc[mt * 4 + nt], al[mt],
                                 bh[nt >> 1][(nt & 1) * 2], bh[nt >> 1][(nt & 1) * 2 + 1]);
            }
        }
    }

    const int er = lane >> 2, ec = (lane & 3) * 2;
    if (Csh) {
        uint32_t* oh = (uint32_t*)Csh;
        uint32_t* ol = (uint32_t*)Csl;
#pragma unroll
        for (int mt = 0; mt < 4; mt++)
#pragma unroll
            for (int nt = 0; nt < 4; nt++) {
                const int row = m0 + wm + mt * 16 + er;
                const int col = n0 + wn + nt * 8 + ec;
                const uint32_t i0 = ((uint32_t)row * N + col) >> 1;
                const uint32_t i1 = i0 + 4u * N;
                float a0 = acc[mt*4+nt][0], a1 = acc[mt*4+nt][1];
                float a2 = acc[mt*4+nt][2], a3 = acc[mt*4+nt][3];
                oh[i0] = pack2(a0, a1);
                ol[i0] = pack2(a0 - bf16r(a0), a1 - bf16r(a1));
                oh[i1] = pack2(a2, a3);
                ol[i1] = pack2(a2 - bf16r(a2), a3 - bf16r(a3));
            }
    } else {
#pragma unroll
        for (int mt = 0; mt < 4; mt++)
#pragma unroll
            for (int nt = 0; nt < 4; nt++) {
                const int row = m0 + wm + mt * 16 + er;
                const int col = n0 + wn + nt * 8 + ec;
                float* cp = C + (size_t)row * N + col;
                *(float2*)cp = make_float2(acc[mt*4+nt][0], acc[mt*4+nt][1]);
                *(float2*)(cp + (size_t)8 * N) = make_float2(acc[mt*4+nt][2], acc[mt*4+nt][3]);
            }
    }
}

// ---------------- fp32 -> bf16 hi/lo split (elementwise) -----------------------
__global__ void __launch_bounds__(256) split_f32(const float* __restrict__ in,
        __nv_bfloat16* __restrict__ hi, __nv_bfloat16* __restrict__ lo, int n4)
{
    const int i = blockIdx.x * 256 + threadIdx.x;
    if (i >= n4) return;
    const float4 v = ((const float4*)in)[i];
    float xs[4] = {v.x, v.y, v.z, v.w};
    union { __nv_bfloat16 b[4]; uint2 u; } H, L;
#pragma unroll
    for (int j = 0; j < 4; j++) {
        __nv_bfloat16 h = __float2bfloat16(xs[j]);
        H.b[j] = h;
        L.b[j] = __float2bfloat16(xs[j] - __bfloat162float(h));
    }
    ((uint2*)hi)[i] = H.u;
    ((uint2*)lo)[i] = L.u;
}

// ---------------- fp32 W[K,N] -> bf16 hi/lo Wt[N,K] (transpose split) ----------
__global__ void __launch_bounds__(256) split_tr(const float* __restrict__ W,
        __nv_bfloat16* __restrict__ hi, __nv_bfloat16* __restrict__ lo, int K, int N)
{
    __shared__ float t[32][33];
    const int n0 = blockIdx.x * 32, k0 = blockIdx.y * 32;
    const int tx = threadIdx.x & 31, ty = threadIdx.x >> 5;
#pragma unroll
    for (int rr = 0; rr < 32; rr += 8)
        t[ty + rr][tx] = W[(size_t)(k0 + ty + rr) * N + n0 + tx];
    __syncthreads();
#pragma unroll
    for (int rr = 0; rr < 32; rr += 8) {
        const float x = t[tx][ty + rr];
        const __nv_bfloat16 h = __float2bfloat16(x);
        const size_t o = (size_t)(n0 + ty + rr) * K + k0 + tx;
        hi[o] = h;
        lo[o] = __float2bfloat16(x - __bfloat162float(h));
    }
}

// ---------------- skinny projection: out[tok,64] = x[tok,2048] @ Wkr[2048,64] ----
__global__ void __launch_bounds__(256) kr_proj(const float* __restrict__ x,
        const float* __restrict__ Wkr, float* __restrict__ out)
{
    __shared__ float sx[4][HIDDEN];
    const int t0 = blockIdx.x * 4;
    for (int f = threadIdx.x; f < 4 * HIDDEN / 4; f += 256) {
        int row = f >> 9, c4 = f & 511;
        ((float4*)sx[row])[c4] = ((const float4*)(x + (size_t)(t0 + row) * HIDDEN))[c4];
    }
    __syncthreads();
    const int n = threadIdx.x & 63, tl = threadIdx.x >> 6;
    float s = 0.f;
#pragma unroll 8
    for (int k = 0; k < HIDDEN; k++) s += sx[tl][k] * Wkr[k * 64 + n];
    out[(size_t)(t0 + tl) * 64 + n] = s;
}

// ---------------- pack q/k -> bf16 hi/lo, row-major [bh][s][192] ----------------
__global__ void __launch_bounds__(256) pack_qk_bf16(const float* __restrict__ cbuf,
        const float* __restrict__ rbuf, int rRowStride, int rHeadStride,
        __nv_bfloat16* __restrict__ Oh, __nv_bfloat16* __restrict__ Ol)
{
    __shared__ float sinv[32];
    const int bh = blockIdx.y, b = bh >> 4, h = bh & 15;
    const int s0 = blockIdx.x * 32;
    if (threadIdx.x < 32)
        sinv[threadIdx.x] = (float)pow(10000.0, -(double)threadIdx.x / 32.0);
    __syncthreads();
    uint32_t* oh = (uint32_t*)Oh;
    uint32_t* ol = (uint32_t*)Ol;
    for (int f = threadIdx.x; f < 32 * 96; f += 256) {
        const int row = f / 96, dp = f % 96, d = dp * 2;
        const size_t tok = (size_t)b * S_ + s0 + row;
        float v0, v1;
        if (d < 128) {
            const float* cp = cbuf + tok * 2048 + h * 128 + d;
            v0 = cp[0]; v1 = cp[1];
        } else {
            const int dd = d - 128, i = dd >> 1;
            const float* rp = rbuf + tok * rRowStride + h * rHeadStride;
            const float re = rp[2 * i], im = rp[2 * i + 1];
            const float ang = (float)(s0 + row) * sinv[i];
            const float cs = cosf(ang), sn = sinf(ang);
            v0 = re * cs - im * sn;
            v1 = re * sn + im * cs;
        }
        const size_t idx = ((size_t)bh * S_ + s0 + row) * 96 + dp;
        oh[idx] = pack2(v0, v1);
        ol[idx] = pack2(v0 - bf16r(v0), v1 - bf16r(v1));
    }
}

// ---------------- pack v -> bf16 hi/lo transposed [bh][d][s] -------------------
__global__ void __launch_bounds__(256) pack_vt_bf16(const float* __restrict__ vt,
        __nv_bfloat16* __restrict__ Vth, __nv_bfloat16* __restrict__ Vtl)
{
    __shared__ float t[64][33];
    const int bh = blockIdx.y, b = bh >> 4, h = bh & 15;
    const int s0 = blockIdx.x * 64, d0 = blockIdx.z * 32;
    for (int f = threadIdx.x; f < 64 * 32; f += 256) {
        const int si = f >> 5, di = f & 31;
        t[si][di] = vt[(size_t)(b * S_ + s0 + si) * 2048 + h * 128 + d0 + di];
    }
    __syncthreads();
    uint32_t* oh = (uint32_t*)Vth;
    uint32_t* ol = (uint32_t*)Vtl;
    for (int f = threadIdx.x; f < 32 * 32; f += 256) {
        const int di = f >> 5, sp = f & 31;
        const float v0 = t[2 * sp][di], v1 = t[2 * sp + 1][di];
        const size_t idx = ((size_t)(bh * 128) + d0 + di) * 1024 + (s0 >> 1) + sp;
        oh[idx] = pack2(v0, v1);
        ol[idx] = pack2(v0 - bf16r(v0), v1 - bf16r(v1));
    }
}

// ---------------- tensor-core causal flash attention (double-buffered K/V) ------
// Q,K: bf16 hi/lo [bh][s][192]; Vt: bf16 hi/lo [bh][d=128][s]
// Output: bf16 hi/lo [tok][h*128+d]
// smem: QH 0, QL 25600 | stage{0,1}: KH +0, KL +25600, VH +51200, VL +69632
#define AQ_STRIDE 400
#define AV_STRIDE 144
#define A_STG 51200
#define STG_SZ 88064
#define ATTN_SMEM 227328

__global__ void __launch_bounds__(128, 1) attn_tc(
        const __nv_bfloat16* __restrict__ Qhg, const __nv_bfloat16* __restrict__ Qlg,
        const __nv_bfloat16* __restrict__ Khg, const __nv_bfloat16* __restrict__ Klg,
        const __nv_bfloat16* __restrict__ Vhg, const __nv_bfloat16* __restrict__ Vlg,
        __nv_bfloat16* __restrict__ Ohg, __nv_bfloat16* __restrict__ Olg)
{
    extern __shared__ char smem[];
    const uint32_t sb = smem_u32(smem);
    const int tid = threadIdx.x, wid = tid >> 5, lane = tid & 31;
    const int bh = blockIdx.y, b = bh >> 4, h = bh & 15;
    const int qt = gridDim.x - 1 - blockIdx.x;
    const int q0 = qt * 64;

    const int er = lane >> 2, ec = (lane & 3) * 2;
    const int aRow = lane & 15, aSel = (lane >> 4) * 16;
    const int bRow = (lane & 7) + ((lane >> 4) << 3), bSel = ((lane >> 3) & 1) * 16;
    const uint32_t qh_base = sb + (wid * 16 + aRow) * AQ_STRIDE + aSel;
    const uint32_t ql_base = sb + 25600 + (wid * 16 + aRow) * AQ_STRIDE + aSel;

    // stage helper: load K/V tile kt2 into buffer bb, then commit
    auto stage = [&](int kt2, int bb) {
        const uint32_t SB = sb + A_STG + bb * STG_SZ;
        const int k0 = kt2 * 64;
        for (int f = tid; f < 1536; f += 128) {
            const int r = f / 24, j = f % 24;
            const size_t src = (size_t)(bh * S_ + k0 + r) * 192 + j * 8;
            cpa16(SB + r * AQ_STRIDE + j * 16, Khg + src);
            cpa16(SB + 25600 + r * AQ_STRIDE + j * 16, Klg + src);
        }
        for (int f = tid; f < 1024; f += 128) {
            const int d = f >> 3, j = f & 7;
            const size_t src = (size_t)(bh * 128 + d) * 2048 + k0 + j * 8;
            cpa16(SB + 51200 + d * AV_STRIDE + j * 16, Vhg + src);
            cpa16(SB + 69632 + d * AV_STRIDE + j * 16, Vlg + src);
        }
        cpa_commit();
    };

    // load Q tile once (group 0)
    for (int f = tid; f < 1536; f += 128) {
        const int r = f / 24, j = f % 24;
        const size_t src = (size_t)(bh * S_ + q0 + r) * 192 + j * 8;
        cpa16(sb + r * AQ_STRIDE + j * 16, Qhg + src);
        cpa16(sb + 25600 + r * AQ_STRIDE + j * 16, Qlg + src);
    }
    cpa_commit();
    // prefetch kt=0 into buffer 0
    stage(0, 0);

    float oacc[16][4];
#pragma unroll
    for (int i = 0; i < 16; i++)
#pragma unroll
        for (int j = 0; j < 4; j++) oacc[i][j] = 0.f;
    float m0 = -1e30f, m1 = -1e30f, l0 = 0.f, l1 = 0.f;

    const float cst = 0.0721687836487032f * 1.44269504088896f;  // 1/sqrt(192)*log2e
    const int lrow0 = wid * 16 + er, lrow1 = lrow0 + 8;

    for (int kt = 0; kt <= qt; kt++) {
        const int buf = kt & 1;
        if (kt < qt) {
            stage(kt + 1, buf ^ 1);   // prefetch next tile into the other buffer
            cpa_wait1();              // current tile (and Q) complete
        } else {
            cpa_wait0();
        }
        __syncthreads();

        const uint32_t SB = sb + A_STG + buf * STG_SZ;
        const uint32_t kh_base = SB + bRow * AQ_STRIDE + bSel;
        const uint32_t kl_base = SB + 25600 + bRow * AQ_STRIDE + bSel;
        const uint32_t vh_base = SB + 51200 + bRow * AV_STRIDE + bSel;
        const uint32_t vl_base = SB + 69632 + bRow * AV_STRIDE + bSel;

        // ---- S = Q K^T (bf16x3) ----
        float sacc[8][4];
#pragma unroll
        for (int i = 0; i < 8; i++)
#pragma unroll
            for (int j = 0; j < 4; j++) sacc[i][j] = 0.f;
#pragma unroll
        for (int ks = 0; ks < 12; ks++) {
            uint32_t ah[4], al4[4];
            ldsm4(ah, qh_base + ks * 32);
            ldsm4(al4, ql_base + ks * 32);
#pragma unroll
            for (int np = 0; np < 4; np++) {
                uint32_t bh4[4], bl4[4];
                ldsm4(bh4, kh_base + np * (16 * AQ_STRIDE) + ks * 32);
                mma16816(sacc[np*2],   ah,  bh4[0], bh4[1]);
                mma16816(sacc[np*2+1], ah,  bh4[2], bh4[3]);
                mma16816(sacc[np*2],   al4, bh4[0], bh4[1]);
                mma16816(sacc[np*2+1], al4, bh4[2], bh4[3]);
                ldsm4(bl4, kl_base + np * (16 * AQ_STRIDE) + ks * 32);
                mma16816(sacc[np*2],   ah,  bl4[0], bl4[1]);
                mma16816(sacc[np*2+1], ah,  bl4[2], bl4[3]);
            }
        }

        // ---- online softmax (base-2) ----
        const bool diag = (kt == qt);
        float mx0 = -1e30f, mx1 = -1e30f;
#pragma unroll
        for (int nt = 0; nt < 8; nt++) {
            const int colb = nt * 8 + ec;
#pragma unroll
            for (int j = 0; j < 2; j++) {
                float v = sacc[nt][j] * cst;
                if (diag && (colb + j) > lrow0) v = -1e30f;
                sacc[nt][j] = v;
                mx0 = fmaxf(mx0, v);
            }
#pragma unroll
            for (int j = 2; j < 4; j++) {
                float v = sacc[nt][j] * cst;
                if (diag && (colb + j - 2) > lrow1) v = -1e30f;
                sacc[nt][j] = v;
                mx1 = fmaxf(mx1, v);
            }
        }
        mx0 = fmaxf(mx0, __shfl_xor_sync(0xffffffffu, mx0, 1));
        mx0 = fmaxf(mx0, __shfl_xor_sync(0xffffffffu, mx0, 2));
        mx1 = fmaxf(mx1, __shfl_xor_sync(0xffffffffu, mx1, 1));
        mx1 = fmaxf(mx1, __shfl_xor_sync(0xffffffffu, mx1, 2));
        const float nm0 = fmaxf(m0, mx0), nm1 = fmaxf(m1, mx1);
        const float c0 = exp2f(m0 - nm0), c1 = exp2f(m1 - nm1);
        m0 = nm0; m1 = nm1;
        float rs0 = 0.f, rs1 = 0.f;
#pragma unroll
        for (int nt = 0; nt < 8; nt++) {
            sacc[nt][0] = exp2f(sacc[nt][0] - nm0);
            sacc[nt][1] = exp2f(sacc[nt][1] - nm0);
            sacc[nt][2] = exp2f(sacc[nt][2] - nm1);
            sacc[nt][3] = exp2f(sacc[nt][3] - nm1);
            rs0 += sacc[nt][0] + sacc[nt][1];
            rs1 += sacc[nt][2] + sacc[nt][3];
        }
        rs0 += __shfl_xor_sync(0xffffffffu, rs0, 1);
        rs0 += __shfl_xor_sync(0xffffffffu, rs0, 2);
        rs1 += __shfl_xor_sync(0xffffffffu, rs1, 1);
        rs1 += __shfl_xor_sync(0xffffffffu, rs1, 2);
        l0 = l0 * c0 + rs0;
        l1 = l1 * c1 + rs1;
#pragma unroll
        for (int i = 0; i < 16; i++) {
            oacc[i][0] *= c0; oacc[i][1] *= c0;
            oacc[i][2] *= c1; oacc[i][3] *= c1;
        }

        // ---- O += P V (bf16x3: PhVh + PlVh + PhVl) ----
#pragma unroll
        for (int ks2 = 0; ks2 < 4; ks2++) {
            const float* s0 = sacc[2 * ks2];
            const float* s1 = sacc[2 * ks2 + 1];
            uint32_t pa[4], pl[4];
            pa[0] = pack2(s0[0], s0[1]);
            pa[1] = pack2(s0[2], s0[3]);
            pa[2] = pack2(s1[0], s1[1]);
            pa[3] = pack2(s1[2], s1[3]);
            pl[0] = pack2(s0[0] - bf16r(s0[0]), s0[1] - bf16r(s0[1]));
            pl[1] = pack2(s0[2] - bf16r(s0[2]), s0[3] - bf16r(s0[3]));
            pl[2] = pack2(s1[0] - bf16r(s1[0]), s1[1] - bf16r(s1[1]));
            pl[3] = pack2(s1[2] - bf16r(s1[2]), s1[3] - bf16r(s1[3]));
#pragma unroll
            for (int np = 0; np < 8; np++) {
                uint32_t vh4[4], vl4[4];
                ldsm4(vh4, vh_base + np * (16 * AV_STRIDE) + ks2 * 32);
                mma16816(oacc[np*2],   pa, vh4[0], vh4[1]);
                mma16816(oacc[np*2+1], pa, vh4[2], vh4[3]);
                mma16816(oacc[np*2],   pl, vh4[0], vh4[1]);
                mma16816(oacc[np*2+1], pl, vh4[2], vh4[3]);
                ldsm4(vl4, vl_base + np * (16 * AV_STRIDE) + ks2 * 32);
                mma16816(oacc[np*2],   pa, vl4[0], vl4[1]);
                mma16816(oacc[np*2+1], pa, vl4[2], vl4[3]);
            }
        }
        __syncthreads();
    }

    // ---- epilogue: normalize, split to bf16 hi/lo, write [tok][h*128+d] --------
    const float i0 = 1.f / l0, i1 = 1.f / l1;
    const int row0 = q0 + wid * 16 + er;
    uint32_t* oh = (uint32_t*)Ohg;
    uint32_t* ol = (uint32_t*)Olg;
#pragma unroll
    for (int nt = 0; nt < 16; nt++) {
        const int col = nt * 8 + ec;
        const float v00 = oacc[nt][0] * i0, v01 = oacc[nt][1] * i0;
        const float v10 = oacc[nt][2] * i1, v11 = oacc[nt][3] * i1;
        const size_t o0 = (((size_t)(b * S_ + row0)) * 2048 + h * 128 + col) >> 1;
        const size_t o1 = (((size_t)(b * S_ + row0 + 8)) * 2048 + h * 128 + col) >> 1;
        oh[o0] = pack2(v00, v01);
        ol[o0] = pack2(v00 - bf16r(v00), v01 - bf16r(v01));
        oh[o1] = pack2(v10, v11);
        ol[o1] = pack2(v10 - bf16r(v10), v11 - bf16r(v11));
    }
}

// ---------------- orchestration -------------------------------------------------
extern "C" void kernel_launch(void* const* d_in, const int* in_sizes, int n_in,
                              void* d_out, int out_size)
{
    const float* x    = (const float*)d_in[0];
    const float* W_c  = (const float*)d_in[1];
    const float* W_cp = (const float*)d_in[2];
    const float* W_qc = (const float*)d_in[3];
    const float* W_qr = (const float*)d_in[4];
    const float* W_kc = (const float*)d_in[5];
    const float* W_kr = (const float*)d_in[6];
    const float* W_v  = (const float*)d_in[7];
    const float* W_o  = (const float*)d_in[8];
    float* out = (float*)d_out;

    float *qc, *qr, *kc, *kr, *vt;
    cudaGetSymbolAddress((void**)&qc,   g_qc);
    cudaGetSymbolAddress((void**)&qr,   g_qr);
    cudaGetSymbolAddress((void**)&kc,   g_kc);
    cudaGetSymbolAddress((void**)&kr,   g_kr);
    cudaGetSymbolAddress((void**)&vt,   g_vt);

    __nv_bfloat16 *xh,*xl,*cph,*cpl,*ch,*cl,*ah,*al;
    __nv_bfloat16 *Qh,*Ql,*Kh,*Kl,*Vth,*Vtl;
    __nv_bfloat16 *wcph,*wcpl,*wch,*wcl,*wqch,*wqcl,*wqrh,*wqrl,*wkch,*wkcl,*wvh,*wvl,*woh,*wol;
    cudaGetSymbolAddress((void**)&xh,  g_xh);   cudaGetSymbolAddress((void**)&xl,  g_xl);
    cudaGetSymbolAddress((void**)&cph, g_cph);  cudaGetSymbolAddress((void**)&cpl, g_cpl);
    cudaGetSymbolAddress((void**)&ch,  g_ch);   cudaGetSymbolAddress((void**)&cl,  g_cl);
    cudaGetSymbolAddress((void**)&ah,  g_ah);   cudaGetSymbolAddress((void**)&al,  g_al);
    cudaGetSymbolAddress((void**)&Qh,  g_Qh);   cudaGetSymbolAddress((void**)&Ql,  g_Ql);
    cudaGetSymbolAddress((void**)&Kh,  g_Kh);   cudaGetSymbolAddress((void**)&Kl,  g_Kl);
    cudaGetSymbolAddress((void**)&Vth, g_Vth);  cudaGetSymbolAddress((void**)&Vtl, g_Vtl);
    cudaGetSymbolAddress((void**)&wcph,g_wcp_h);cudaGetSymbolAddress((void**)&wcpl,g_wcp_l);
    cudaGetSymbolAddress((void**)&wch, g_wc_h); cudaGetSymbolAddress((void**)&wcl, g_wc_l);
    cudaGetSymbolAddress((void**)&wqch,g_wqc_h);cudaGetSymbolAddress((void**)&wqcl,g_wqc_l);
    cudaGetSymbolAddress((void**)&wqrh,g_wqr_h);cudaGetSymbolAddress((void**)&wqrl,g_wqr_l);
    cudaGetSymbolAddress((void**)&wkch,g_wkc_h);cudaGetSymbolAddress((void**)&wkcl,g_wkc_l);
    cudaGetSymbolAddress((void**)&wvh, g_wv_h); cudaGetSymbolAddress((void**)&wvl, g_wv_l);
    cudaGetSymbolAddress((void**)&woh, g_wo_h); cudaGetSymbolAddress((void**)&wol, g_wo_l);

    cudaFuncSetAttribute(mma_gemm,
                         cudaFuncAttributeMaxDynamicSharedMemorySize, MG_SMEM);
    cudaFuncSetAttribute(attn_tc,
                         cudaFuncAttributeMaxDynamicSharedMemorySize, ATTN_SMEM);

    dim3 blk(256);
    // input + weight splits
    split_f32<<<(TOKENS*HIDDEN/4 + 255)/256, blk>>>(x, xh, xl, TOKENS*HIDDEN/4);
    split_tr<<<dim3(1536/32, 2048/32), blk>>>(W_cp, wcph, wcpl, 2048, 1536);
    split_tr<<<dim3(512/32,  2048/32), blk>>>(W_c,  wch,  wcl,  2048, 512);
    split_tr<<<dim3(2048/32, 1536/32), blk>>>(W_qc, wqch, wqcl, 1536, 2048);
    split_tr<<<dim3(1024/32, 1536/32), blk>>>(W_qr, wqrh, wqrl, 1536, 1024);
    split_tr<<<dim3(2048/32, 512/32),  blk>>>(W_kc, wkch, wkcl, 512, 2048);
    split_tr<<<dim3(2048/32, 512/32),  blk>>>(W_v,  wvh,  wvl,  512, 2048);
    split_tr<<<dim3(2048/32, 2048/32), blk>>>(W_o,  woh,  wol,  2048, 2048);
    // latent projections (split bf16 output — skips split_f32 passes)
    mma_gemm<<<dim3(1536/128, TOKENS/128), blk, MG_SMEM>>>(xh, xl, wcph, wcpl,
        nullptr, cph, cpl, TOKENS, 1536, 2048);
    mma_gemm<<<dim3(512/128, TOKENS/128), blk, MG_SMEM>>>(xh, xl, wch, wcl,
        nullptr, ch, cl, TOKENS, 512, 2048);
    kr_proj<<<TOKENS/4, blk>>>(x, W_kr, kr);
    // q/k/v heads (fp32 out, consumed by pack kernels)
    mma_gemm<<<dim3(2048/128, TOKENS/128), blk, MG_SMEM>>>(cph, cpl, wqch, wqcl,
        qc, nullptr, nullptr, TOKENS, 2048, 1536);
    mma_gemm<<<dim3(1024/128, TOKENS/128), blk, MG_SMEM>>>(cph, cpl, wqrh, wqrl,
        qr, nullptr, nullptr, TOKENS, 1024, 1536);
    mma_gemm<<<dim3(2048/128, TOKENS/128), blk, MG_SMEM>>>(ch, cl, wkch, wkcl,
        kc, nullptr, nullptr, TOKENS, 2048, 512);
    mma_gemm<<<dim3(2048/128, TOKENS/128), blk, MG_SMEM>>>(ch, cl, wvh, wvl,
        vt, nullptr, nullptr, TOKENS, 2048, 512);
    // pack + rope -> bf16 hi/lo attention operands
    pack_qk_bf16<<<dim3(S_/32, BH), blk>>>(qc, qr, NHEADS*DR, DR, Qh, Ql);
    pack_qk_bf16<<<dim3(S_/32, BH), blk>>>(kc, kr, DR, 0, Kh, Kl);
    pack_vt_bf16<<<dim3(S_/64, BH, 4), blk>>>(vt, Vth, Vtl);
    // tensor-core causal flash attention (double-buffered K/V)
    attn_tc<<<dim3(S_/64, BH), dim3(128), ATTN_SMEM>>>(Qh, Ql, Kh, Kl, Vth, Vtl, ah, al);
    // output projection
    mma_gemm<<<dim3(2048/128, TOKENS/128), blk, MG_SMEM>>>(ah, al, woh, wol,
        out, nullptr, nullptr, TOKENS, 2048, 2048);
}